// round 10
// baseline (speedup 1.0000x reference)
#include <cuda_runtime.h>
#include <cuda_bf16.h>
#include <math.h>

// Problem constants
#define S_LEN 2048
#define HIDDEN 2560
#define NH 32
#define NKV 8
#define HD 128
#define QDIM (NH*HD)    // 4096
#define KVDIM (NKV*HD)  // 1024
#define GS 128

// -------- scratch (static device arrays; no allocation allowed) --------
__device__ float g_q[S_LEN * QDIM];            // Q fp32 (roped in-place)
__device__ float g_k[S_LEN * KVDIM];           // K fp32 (pre-rope)
__device__ float g_v[S_LEN * KVDIM];           // V fp32
__device__ __nv_bfloat16 g_xh[S_LEN * HIDDEN], g_xl[S_LEN * HIDDEN];
__device__ __nv_bfloat16 g_kh[S_LEN * KVDIM], g_kl[S_LEN * KVDIM];
__device__ __nv_bfloat16 g_vh[S_LEN * KVDIM], g_vl[S_LEN * KVDIM];
__device__ __nv_bfloat16 g_ah[S_LEN * QDIM],  g_al[S_LEN * QDIM];

// ======================================================================
// helpers
// ======================================================================
__device__ __forceinline__ void split2(float f0, float f1,
                                       unsigned &hi, unsigned &lo) {
    __nv_bfloat16 h0 = __float2bfloat16(f0);
    __nv_bfloat16 h1 = __float2bfloat16(f1);
    __nv_bfloat16 l0 = __float2bfloat16(f0 - __bfloat162float(h0));
    __nv_bfloat16 l1 = __float2bfloat16(f1 - __bfloat162float(h1));
    hi = (unsigned)__bfloat16_as_ushort(h0) |
         ((unsigned)__bfloat16_as_ushort(h1) << 16);
    lo = (unsigned)__bfloat16_as_ushort(l0) |
         ((unsigned)__bfloat16_as_ushort(l1) << 16);
}

__device__ __forceinline__ unsigned pack2(float f0, float f1) {
    return (unsigned)__bfloat16_as_ushort(__float2bfloat16(f0)) |
           ((unsigned)__bfloat16_as_ushort(__float2bfloat16(f1)) << 16);
}

__device__ __forceinline__ void mma_bf16(float c[4],
                                         unsigned a0, unsigned a1, unsigned a2, unsigned a3,
                                         unsigned b0, unsigned b1) {
    asm volatile(
        "mma.sync.aligned.m16n8k16.row.col.f32.bf16.bf16.f32 "
        "{%0,%1,%2,%3}, {%4,%5,%6,%7}, {%8,%9}, {%0,%1,%2,%3};"
        : "+f"(c[0]), "+f"(c[1]), "+f"(c[2]), "+f"(c[3])
        : "r"(a0), "r"(a1), "r"(a2), "r"(a3), "r"(b0), "r"(b1));
}

__device__ __forceinline__ void ldsm_x2_trans(unsigned &r0, unsigned &r1, unsigned addr) {
    asm volatile("ldmatrix.sync.aligned.m8n8.x2.trans.shared.b16 {%0,%1}, [%2];"
                 : "=r"(r0), "=r"(r1) : "r"(addr));
}

__device__ __forceinline__ unsigned smem_u32(const void* p) {
    return (unsigned)__cvta_generic_to_shared(p);
}

__device__ __forceinline__ void cp_async16(unsigned dst, const void* src) {
    asm volatile("cp.async.cg.shared.global [%0], [%1], 16;" :: "r"(dst), "l"(src));
}
#define CP_COMMIT() asm volatile("cp.async.commit_group;" ::: "memory")
#define CP_WAIT0()  asm volatile("cp.async.wait_group 0;" ::: "memory")

// ======================================================================
// presplit: x fp32 -> bf16 hi/lo planes
// ======================================================================
__global__ __launch_bounds__(256)
void presplit_kernel(const float* __restrict__ x,
                     __nv_bfloat16* __restrict__ xh,
                     __nv_bfloat16* __restrict__ xl)
{
    int i = blockIdx.x * 256 + threadIdx.x;
    float2 v = ((const float2*)x)[i];
    unsigned h, l;
    split2(v.x, v.y, h, l);
    ((unsigned*)xh)[i] = h;
    ((unsigned*)xl)[i] = l;
}

// ======================================================================
// Dequant GEMM core (validated R8): presplit A + exact-int4 B + scale fold
// ======================================================================
#define BM 128
#define BN 128
#define BK 32
#define GST 20
#define GPL (128 * GST)
#define GBUF (3 * GPL)

__device__ __forceinline__ void gemm_core(
    const __nv_bfloat16* __restrict__ Ahp,
    const __nv_bfloat16* __restrict__ Alp,
    const int*   __restrict__ qw,
    const float* __restrict__ sc,
    const int*   __restrict__ qz,
    const float* __restrict__ bias,
    float* __restrict__ C,
    int N, int K, int bm, int bn, unsigned* gsm)
{
    unsigned sbase = smem_u32(gsm);

    int tid  = threadIdx.x;
    int lane = tid & 31;
    int warp = tid >> 5;
    int warp_m = warp & 1;
    int warp_n = warp >> 1;
    int t = lane & 3;
    int g = lane >> 2;

    int am[2], ach[2];
#pragma unroll
    for (int i = 0; i < 2; i++) {
        int c = tid + i * 256;
        am[i]  = c >> 2;
        ach[i] = c & 3;
    }
    int n_loc = tid & 127;
    int kp0   = (tid >> 7) << 1;

    int scol[4];
#pragma unroll
    for (int ni = 0; ni < 4; ni++)
        scol[ni] = bn + warp_n * 32 + ni * 8 + (t << 1);

    float acc[4][4][4];
#pragma unroll
    for (int mi = 0; mi < 4; mi++)
#pragma unroll
        for (int ni = 0; ni < 4; ni++)
#pragma unroll
            for (int r = 0; r < 4; r++) acc[mi][ni][r] = 0.f;

    float sreg[4][2];
    unsigned bw[2];
    float bz;

    int T = K / BK;

    {
        unsigned b0 = sbase;
#pragma unroll
        for (int i = 0; i < 2; i++) {
            const __nv_bfloat16* sh = Ahp + (size_t)(bm + am[i]) * K + ach[i] * 8;
            const __nv_bfloat16* sl = Alp + (size_t)(bm + am[i]) * K + ach[i] * 8;
            unsigned d = (unsigned)(am[i] * GST + ach[i] * 4) * 4;
            cp_async16(b0 + d, sh);
            cp_async16(b0 + GPL * 4 + d, sl);
        }
        CP_COMMIT();
        const int* qp = qw + (size_t)kp0 * N + bn + n_loc;
        bw[0] = (unsigned)qp[0];
        bw[1] = (unsigned)qp[N];
        bz = (float)qz[bn + n_loc];
        unsigned* Bs = gsm + 2 * GPL;
#pragma unroll
        for (int i = 0; i < 2; i++) {
            unsigned q = bw[i];
            int kpb = (kp0 + i) * 4;
#pragma unroll
            for (int j = 0; j < 4; j++)
                Bs[n_loc * GST + kpb + j] =
                    pack2((float)((q >> (8 * j)) & 15u) - bz,
                          (float)((q >> (8 * j + 4)) & 15u) - bz);
        }
        if (T > 1) {
            const int* qp1 = qw + (size_t)(4 + kp0) * N + bn + n_loc;
            bw[0] = (unsigned)qp1[0];
            bw[1] = (unsigned)qp1[N];
            bz = (float)qz[(size_t)(BK >> 7) * N + bn + n_loc];
        }
        CP_WAIT0();
        __syncthreads();
    }

    for (int it = 0; it < T; it++) {
        int k0 = it * BK;
        int b = it & 1;
        unsigned* base = gsm + b * GBUF;
        bool hasNext = (it + 1 < T);

        if (hasNext) {
            int kn = k0 + BK;
            unsigned nb = sbase + ((b ^ 1) * GBUF) * 4;
#pragma unroll
            for (int i = 0; i < 2; i++) {
                const __nv_bfloat16* sh = Ahp + (size_t)(bm + am[i]) * K + kn + ach[i] * 8;
                const __nv_bfloat16* sl = Alp + (size_t)(bm + am[i]) * K + kn + ach[i] * 8;
                unsigned d = (unsigned)(am[i] * GST + ach[i] * 4) * 4;
                cp_async16(nb + d, sh);
                cp_async16(nb + GPL * 4 + d, sl);
            }
            CP_COMMIT();
            unsigned* nBs = gsm + (b ^ 1) * GBUF + 2 * GPL;
#pragma unroll
            for (int i = 0; i < 2; i++) {
                unsigned q = bw[i];
                int kpb = (kp0 + i) * 4;
#pragma unroll
                for (int j = 0; j < 4; j++)
                    nBs[n_loc * GST + kpb + j] =
                        pack2((float)((q >> (8 * j)) & 15u) - bz,
                              (float)((q >> (8 * j + 4)) & 15u) - bz);
            }
            if (it + 2 < T) {
                int kn2 = k0 + 2 * BK;
                const int* qp = qw + (size_t)((kn2 >> 3) + kp0) * N + bn + n_loc;
                bw[0] = (unsigned)qp[0];
                bw[1] = (unsigned)qp[N];
                bz = (float)qz[(size_t)(kn2 >> 7) * N + bn + n_loc];
            }
        }

        if ((k0 & 127) == 0) {
            int grp = k0 >> 7;
#pragma unroll
            for (int ni = 0; ni < 4; ni++) {
                sreg[ni][0] = sc[(size_t)grp * N + scol[ni]];
                sreg[ni][1] = sc[(size_t)grp * N + scol[ni] + 1];
            }
        }

        const unsigned* AsH = base;
        const unsigned* AsL = base + GPL;
        const unsigned* Bs  = base + 2 * GPL;
        unsigned ah[2][4][4], al[2][4][4], bh[2][4][2];
#pragma unroll
        for (int ks = 0; ks < 2; ks++) {
            int kpb = ks * 8;
#pragma unroll
            for (int mi = 0; mi < 4; mi++) {
                int r = warp_m * 64 + mi * 16 + g;
                ah[ks][mi][0] = AsH[r * GST + kpb + t];
                ah[ks][mi][1] = AsH[(r + 8) * GST + kpb + t];
                ah[ks][mi][2] = AsH[r * GST + kpb + t + 4];
                ah[ks][mi][3] = AsH[(r + 8) * GST + kpb + t + 4];
                al[ks][mi][0] = AsL[r * GST + kpb + t];
                al[ks][mi][1] = AsL[(r + 8) * GST + kpb + t];
                al[ks][mi][2] = AsL[r * GST + kpb + t + 4];
                al[ks][mi][3] = AsL[(r + 8) * GST + kpb + t + 4];
            }
#pragma unroll
            for (int ni = 0; ni < 4; ni++) {
                int c = warp_n * 32 + ni * 8 + g;
                bh[ks][ni][0] = Bs[c * GST + kpb + t];
                bh[ks][ni][1] = Bs[c * GST + kpb + t + 4];
            }
        }

        float tmp[2][4];
#pragma unroll
        for (int u = 0; u < 16; u++) {
            int mi = u >> 2, ni = u & 3, pb = u & 1;
            tmp[pb][0] = 0.f; tmp[pb][1] = 0.f;
            tmp[pb][2] = 0.f; tmp[pb][3] = 0.f;
            mma_bf16(tmp[pb], ah[0][mi][0], ah[0][mi][1], ah[0][mi][2], ah[0][mi][3],
                     bh[0][ni][0], bh[0][ni][1]);
            mma_bf16(tmp[pb], al[0][mi][0], al[0][mi][1], al[0][mi][2], al[0][mi][3],
                     bh[0][ni][0], bh[0][ni][1]);
            mma_bf16(tmp[pb], ah[1][mi][0], ah[1][mi][1], ah[1][mi][2], ah[1][mi][3],
                     bh[1][ni][0], bh[1][ni][1]);
            mma_bf16(tmp[pb], al[1][mi][0], al[1][mi][1], al[1][mi][2], al[1][mi][3],
                     bh[1][ni][0], bh[1][ni][1]);
            if (u > 0) {
                int v = u - 1, vm = v >> 2, vn = v & 3, vb = v & 1;
                acc[vm][vn][0] += tmp[vb][0] * sreg[vn][0];
                acc[vm][vn][1] += tmp[vb][1] * sreg[vn][1];
                acc[vm][vn][2] += tmp[vb][2] * sreg[vn][0];
                acc[vm][vn][3] += tmp[vb][3] * sreg[vn][1];
            }
        }
        acc[3][3][0] += tmp[1][0] * sreg[3][0];
        acc[3][3][1] += tmp[1][1] * sreg[3][1];
        acc[3][3][2] += tmp[1][2] * sreg[3][0];
        acc[3][3][3] += tmp[1][3] * sreg[3][1];

        if (hasNext) CP_WAIT0();
        __syncthreads();
    }

#pragma unroll
    for (int ni = 0; ni < 4; ni++) {
        int n = scol[ni];
        float b0 = 0.f, b1 = 0.f;
        if (bias) { b0 = bias[n]; b1 = bias[n + 1]; }
#pragma unroll
        for (int mi = 0; mi < 4; mi++) {
            int m = bm + warp_m * 64 + mi * 16 + g;
            float2 v0 = make_float2(acc[mi][ni][0] + b0, acc[mi][ni][1] + b1);
            float2 v1 = make_float2(acc[mi][ni][2] + b0, acc[mi][ni][3] + b1);
            *(float2*)(C + (size_t)m * N + n) = v0;
            *(float2*)(C + (size_t)(m + 8) * N + n) = v1;
        }
    }
}

__global__ __launch_bounds__(256, 2)
void gemm_qkv_kernel(const __nv_bfloat16* __restrict__ xh,
                     const __nv_bfloat16* __restrict__ xl,
    const int* __restrict__ qwq, const float* __restrict__ scq,
    const int* __restrict__ qzq, const float* __restrict__ bq,
    const int* __restrict__ qwk, const float* __restrict__ sck,
    const int* __restrict__ qzk, const float* __restrict__ bk,
    const int* __restrict__ qwv, const float* __restrict__ scv,
    const int* __restrict__ qzv, const float* __restrict__ bv,
    float* __restrict__ Cq, float* __restrict__ Ck, float* __restrict__ Cv)
{
    extern __shared__ unsigned gsm[];
    int bt = blockIdx.x;
    int bm = blockIdx.y * BM;
    const int* qw; const float* sc; const int* qz; const float* bias;
    float* C; int N; int bn;
    if (bt < 32)      { qw = qwq; sc = scq; qz = qzq; bias = bq; C = Cq; N = QDIM;  bn = bt * BN; }
    else if (bt < 40) { qw = qwk; sc = sck; qz = qzk; bias = bk; C = Ck; N = KVDIM; bn = (bt - 32) * BN; }
    else              { qw = qwv; sc = scv; qz = qzv; bias = bv; C = Cv; N = KVDIM; bn = (bt - 40) * BN; }
    gemm_core(xh, xl, qw, sc, qz, bias, C, N, HIDDEN, bm, bn, gsm);
}

__global__ __launch_bounds__(256, 2)
void gemm_o_kernel(const __nv_bfloat16* __restrict__ ah,
                   const __nv_bfloat16* __restrict__ al,
                   const int* __restrict__ qw, const float* __restrict__ sc,
                   const int* __restrict__ qz, float* __restrict__ C)
{
    extern __shared__ unsigned gsm[];
    gemm_core(ah, al, qw, sc, qz, nullptr, C, HIDDEN, QDIM,
              blockIdx.y * BM, blockIdx.x * BN, gsm);
}

// ======================================================================
// RoPE + split (unchanged)
// ======================================================================
__global__ __launch_bounds__(256)
void rope_split_kernel(float* __restrict__ Qb,
                       const float* __restrict__ Kf,
                       const float* __restrict__ Vf,
                       __nv_bfloat16* __restrict__ Kh, __nv_bfloat16* __restrict__ Kl,
                       __nv_bfloat16* __restrict__ Vh, __nv_bfloat16* __restrict__ Vl,
                       const float* __restrict__ cosb,
                       const float* __restrict__ sinb)
{
    int s = blockIdx.y;
    int h = blockIdx.x * 4 + (threadIdx.x >> 6);
    int d = threadIdx.x & 63;

    if (h < NH) {
        float c1 = cosb[s * HD + d],     s1 = sinb[s * HD + d];
        float c2 = cosb[s * HD + d + 64], s2 = sinb[s * HD + d + 64];
        float* base = Qb + (size_t)s * QDIM + h * HD;
        float x1 = base[d], x2 = base[d + 64];
        base[d]      = x1 * c1 - x2 * s1;
        base[d + 64] = x2 * c2 + x1 * s2;
    } else if (h < NH + NKV) {
        int kh = h - NH;
        float c1 = cosb[s * HD + d],     s1 = sinb[s * HD + d];
        float c2 = cosb[s * HD + d + 64], s2 = sinb[s * HD + d + 64];
        const float* base = Kf + (size_t)s * KVDIM + kh * HD;
        float x1 = base[d], x2 = base[d + 64];
        float y1 = x1 * c1 - x2 * s1;
        float y2 = x2 * c2 + x1 * s2;
        size_t o = (size_t)s * KVDIM + kh * HD + d;
        __nv_bfloat16 h1 = __float2bfloat16(y1);
        __nv_bfloat16 h2 = __float2bfloat16(y2);
        Kh[o] = h1;       Kl[o] = __float2bfloat16(y1 - __bfloat162float(h1));
        Kh[o + 64] = h2;  Kl[o + 64] = __float2bfloat16(y2 - __bfloat162float(h2));
    } else {
        int vh = h - NH - NKV;
        const float* base = Vf + (size_t)s * KVDIM + vh * HD;
        float x1 = base[d], x2 = base[d + 64];
        size_t o = (size_t)s * KVDIM + vh * HD + d;
        __nv_bfloat16 h1 = __float2bfloat16(x1);
        __nv_bfloat16 h2 = __float2bfloat16(x2);
        Vh[o] = h1;       Vl[o] = __float2bfloat16(x1 - __bfloat162float(h1));
        Vh[o + 64] = h2;  Vl[o + 64] = __float2bfloat16(x2 - __bfloat162float(h2));
    }
}

// ======================================================================
// bf16x3 flash attention: FBQ=64, 128-thread CTAs, 2 CTAs/SM.
// ======================================================================
#define FBQ 64
#define FBK 64
#define FTHREADS 128
#define KVW 68
#define FPLANE (FBK * KVW)

__global__ __launch_bounds__(FTHREADS, 2)
void flash_tc_kernel(const float* __restrict__ Q,
                     const __nv_bfloat16* __restrict__ Kh,
                     const __nv_bfloat16* __restrict__ Kl,
                     const __nv_bfloat16* __restrict__ Vh,
                     const __nv_bfloat16* __restrict__ Vl,
                     __nv_bfloat16* __restrict__ Oh,
                     __nv_bfloat16* __restrict__ Ol)
{
    extern __shared__ unsigned fsm[];
    unsigned (*KsH)[KVW] = (unsigned(*)[KVW])(fsm);
    unsigned (*KsL)[KVW] = (unsigned(*)[KVW])(fsm + FPLANE);
    unsigned (*VsH)[KVW] = (unsigned(*)[KVW])(fsm + 2 * FPLANE);
    unsigned (*VsL)[KVW] = (unsigned(*)[KVW])(fsm + 3 * FPLANE);

    int h = blockIdx.y;
    int qt = gridDim.x - 1 - blockIdx.x;   // largest q-tile first
    int q0 = qt * FBQ;
    int kvh = h >> 2;
    int tid = threadIdx.x, lane = tid & 31, warp = tid >> 5;   // warp 0..3
    int t = lane & 3, g = lane >> 2;

    unsigned kbH = smem_u32(KsH), kbL = smem_u32(KsL);
    unsigned vbH = smem_u32(VsH), vbL = smem_u32(VsL);

    // ---- Q fragments, scale folded, split hi/lo (regs) ----
    unsigned qh[8][4], ql[8][4];
    {
        const float sc = 0.08838834764831845f;
        int r0 = q0 + warp * 16 + g;
        const float* p0 = Q + (size_t)r0 * QDIM + h * HD;
        const float* p1 = p0 + 8 * QDIM;
#pragma unroll
        for (int ks = 0; ks < 8; ks++) {
            int d = ks * 16 + 2 * t;
            float2 a0 = *(const float2*)(p0 + d);
            float2 a1 = *(const float2*)(p1 + d);
            float2 a2 = *(const float2*)(p0 + d + 8);
            float2 a3 = *(const float2*)(p1 + d + 8);
            split2(a0.x * sc, a0.y * sc, qh[ks][0], ql[ks][0]);
            split2(a1.x * sc, a1.y * sc, qh[ks][1], ql[ks][1]);
            split2(a2.x * sc, a2.y * sc, qh[ks][2], ql[ks][2]);
            split2(a3.x * sc, a3.y * sc, qh[ks][3], ql[ks][3]);
        }
    }

    float m0 = -INFINITY, m1 = -INFINITY, l0s = 0.f, l1s = 0.f;
    float o_acc[16][4];
#pragma unroll
    for (int nj = 0; nj < 16; nj++)
#pragma unroll
        for (int r = 0; r < 4; r++) o_acc[nj][r] = 0.f;

    int ntiles = qt + 1;
    for (int tt = 0; tt < ntiles; tt++) {
        int kb = tt << 6;
        __syncthreads();
        // ---- cp.async K/V tiles (1024 chunks/plane; 8 per thread) ----
#pragma unroll
        for (int i = 0; i < 8; i++) {
            int idx = tid + i * FTHREADS;
            int r = idx >> 4;
            int ch = idx & 15;
            size_t off = (size_t)(kb + r) * KVDIM + kvh * HD + ch * 8;
            unsigned d = (unsigned)(r * KVW + ch * 4) * 4;
            cp_async16(kbH + d, Kh + off);
            cp_async16(kbL + d, Kl + off);
            cp_async16(vbH + d, Vh + off);
            cp_async16(vbL + d, Vl + off);
        }
        CP_COMMIT();
        CP_WAIT0();
        __syncthreads();

        // ---- scores S = Q K^T (bf16x3) ----
        float s[8][4];
#pragma unroll
        for (int ni = 0; ni < 8; ni++)
#pragma unroll
            for (int r = 0; r < 4; r++) s[ni][r] = 0.f;

#pragma unroll
        for (int ks = 0; ks < 8; ks++) {
            int w = ks * 8 + t;
#pragma unroll
            for (int ni = 0; ni < 8; ni++) {
                int col = ni * 8 + g;
                unsigned bh0 = KsH[col][w], bh1 = KsH[col][w + 4];
                unsigned bl0 = KsL[col][w], bl1 = KsL[col][w + 4];
                mma_bf16(s[ni], qh[ks][0], qh[ks][1], qh[ks][2], qh[ks][3], bh0, bh1);
                mma_bf16(s[ni], qh[ks][0], qh[ks][1], qh[ks][2], qh[ks][3], bl0, bl1);
                mma_bf16(s[ni], ql[ks][0], ql[ks][1], ql[ks][2], ql[ks][3], bh0, bh1);
            }
        }

        // ---- causal mask (diagonal tile only) ----
        if (kb + FBK > q0) {
            int r0 = q0 + warp * 16 + g, r1 = r0 + 8;
#pragma unroll
            for (int ni = 0; ni < 8; ni++) {
                int c0 = kb + ni * 8 + 2 * t, c1 = c0 + 1;
                if (c0 > r0) s[ni][0] = -INFINITY;
                if (c1 > r0) s[ni][1] = -INFINITY;
                if (c0 > r1) s[ni][2] = -INFINITY;
                if (c1 > r1) s[ni][3] = -INFINITY;
            }
        }

        // ---- online softmax ----
        float rm0 = -INFINITY, rm1 = -INFINITY;
#pragma unroll
        for (int ni = 0; ni < 8; ni++) {
            rm0 = fmaxf(rm0, fmaxf(s[ni][0], s[ni][1]));
            rm1 = fmaxf(rm1, fmaxf(s[ni][2], s[ni][3]));
        }
        rm0 = fmaxf(rm0, __shfl_xor_sync(0xffffffffu, rm0, 1));
        rm0 = fmaxf(rm0, __shfl_xor_sync(0xffffffffu, rm0, 2));
        rm1 = fmaxf(rm1, __shfl_xor_sync(0xffffffffu, rm1, 1));
        rm1 = fmaxf(rm1, __shfl_xor_sync(0xffffffffu, rm1, 2));
        float mn0 = fmaxf(m0, rm0), mn1 = fmaxf(m1, rm1);
        float cr0 = __expf(m0 - mn0), cr1 = __expf(m1 - mn1);
        m0 = mn0; m1 = mn1;
        float ps0 = 0.f, ps1 = 0.f;
#pragma unroll
        for (int ni = 0; ni < 8; ni++) {
            s[ni][0] = __expf(s[ni][0] - mn0);
            s[ni][1] = __expf(s[ni][1] - mn0);
            s[ni][2] = __expf(s[ni][2] - mn1);
            s[ni][3] = __expf(s[ni][3] - mn1);
            ps0 += s[ni][0] + s[ni][1];
            ps1 += s[ni][2] + s[ni][3];
        }
        ps0 += __shfl_xor_sync(0xffffffffu, ps0, 1);
        ps0 += __shfl_xor_sync(0xffffffffu, ps0, 2);
        ps1 += __shfl_xor_sync(0xffffffffu, ps1, 1);
        ps1 += __shfl_xor_sync(0xffffffffu, ps1, 2);
        l0s = l0s * cr0 + ps0;
        l1s = l1s * cr1 + ps1;
#pragma unroll
        for (int nj = 0; nj < 16; nj++) {
            o_acc[nj][0] *= cr0; o_acc[nj][1] *= cr0;
            o_acc[nj][2] *= cr1; o_acc[nj][3] *= cr1;
        }

        // ---- O += P V (bf16x3) ----
#pragma unroll
        for (int ks2 = 0; ks2 < 4; ks2++) {
            unsigned ph[4], pl[4];
            split2(s[2 * ks2][0],     s[2 * ks2][1],     ph[0], pl[0]);
            split2(s[2 * ks2][2],     s[2 * ks2][3],     ph[1], pl[1]);
            split2(s[2 * ks2 + 1][0], s[2 * ks2 + 1][1], ph[2], pl[2]);
            split2(s[2 * ks2 + 1][2], s[2 * ks2 + 1][3], ph[3], pl[3]);
            unsigned rowb = (unsigned)(ks2 * 16 + (lane & 15)) * (KVW * 4);
#pragma unroll
            for (int nj = 0; nj < 16; nj++) {
                unsigned v0, v1, u0, u1;
                ldsm_x2_trans(v0, v1, vbH + rowb + nj * 16);
                ldsm_x2_trans(u0, u1, vbL + rowb + nj * 16);
                mma_bf16(o_acc[nj], ph[0], ph[1], ph[2], ph[3], v0, v1);
                mma_bf16(o_acc[nj], ph[0], ph[1], ph[2], ph[3], u0, u1);
                mma_bf16(o_acc[nj], pl[0], pl[1], pl[2], pl[3], v0, v1);
            }
        }
    }

    // ---- epilogue: write bf16 hi/lo planes ----
    float inv0 = 1.f / l0s, inv1 = 1.f / l1s;
    int r0 = q0 + warp * 16 + g;
    size_t b0 = (size_t)r0 * QDIM + h * HD;
    size_t b1 = b0 + 8 * (size_t)QDIM;
#pragma unroll
    for (int nj = 0; nj < 16; nj++) {
        int d = nj * 8 + 2 * t;
        unsigned hh, ll;
        split2(o_acc[nj][0] * inv0, o_acc[nj][1] * inv0, hh, ll);
        *(unsigned*)(Oh + b0 + d) = hh;
        *(unsigned*)(Ol + b0 + d) = ll;
        split2(o_acc[nj][2] * inv1, o_acc[nj][3] * inv1, hh, ll);
        *(unsigned*)(Oh + b1 + d) = hh;
        *(unsigned*)(Ol + b1 + d) = ll;
    }
}

// ======================================================================
// Launch
// ======================================================================
extern "C" void kernel_launch(void* const* d_in, const int* in_sizes, int n_in,
                              void* d_out, int out_size)
{
    const float* x        = (const float*)d_in[0];
    const float* cosb     = (const float*)d_in[1];
    const float* sinb     = (const float*)d_in[2];
    const float* q_scales = (const float*)d_in[3];
    const float* q_bias   = (const float*)d_in[4];
    const float* k_scales = (const float*)d_in[5];
    const float* k_bias   = (const float*)d_in[6];
    const float* v_scales = (const float*)d_in[7];
    const float* v_bias   = (const float*)d_in[8];
    const float* o_scales = (const float*)d_in[9];
    const int* q_qweight  = (const int*)d_in[10];
    const int* q_qzeros   = (const int*)d_in[11];
    const int* k_qweight  = (const int*)d_in[12];
    const int* k_qzeros   = (const int*)d_in[13];
    const int* v_qweight  = (const int*)d_in[14];
    const int* v_qzeros   = (const int*)d_in[15];
    const int* o_qweight  = (const int*)d_in[16];
    const int* o_qzeros   = (const int*)d_in[17];
    float* out = (float*)d_out;

    float *pq, *pk, *pv;
    __nv_bfloat16 *pxh, *pxl, *pkh, *pkl, *pvh, *pvl, *pah, *pal;
    cudaGetSymbolAddress((void**)&pq, g_q);
    cudaGetSymbolAddress((void**)&pk, g_k);
    cudaGetSymbolAddress((void**)&pv, g_v);
    cudaGetSymbolAddress((void**)&pxh, g_xh);
    cudaGetSymbolAddress((void**)&pxl, g_xl);
    cudaGetSymbolAddress((void**)&pkh, g_kh);
    cudaGetSymbolAddress((void**)&pkl, g_kl);
    cudaGetSymbolAddress((void**)&pvh, g_vh);
    cudaGetSymbolAddress((void**)&pvl, g_vl);
    cudaGetSymbolAddress((void**)&pah, g_ah);
    cudaGetSymbolAddress((void**)&pal, g_al);

    size_t gsmem = (size_t)(2 * GBUF) * sizeof(unsigned);
    cudaFuncSetAttribute(gemm_qkv_kernel,
                         cudaFuncAttributeMaxDynamicSharedMemorySize, (int)gsmem);
    cudaFuncSetAttribute(gemm_o_kernel,
                         cudaFuncAttributeMaxDynamicSharedMemorySize, (int)gsmem);

    // presplit x
    presplit_kernel<<<(S_LEN * HIDDEN / 2) / 256, 256>>>(x, pxh, pxl);

    // fused QKV projection
    {
        dim3 grid(48, S_LEN / BM);
        gemm_qkv_kernel<<<grid, 256, gsmem>>>(
            pxh, pxl,
            q_qweight, q_scales, q_qzeros, q_bias,
            k_qweight, k_scales, k_qzeros, k_bias,
            v_qweight, v_scales, v_qzeros, v_bias,
            pq, pk, pv);
    }

    // RoPE (Q in-place) + K/V presplit
    {
        dim3 grid(12, S_LEN);
        rope_split_kernel<<<grid, 256>>>(pq, pk, pv, pkh, pkl, pvh, pvl, cosb, sinb);
    }

    // Flash attention (64-row tiles, 128-thread CTAs, 2 CTAs/SM)
    {
        size_t smem = (size_t)(4 * FPLANE) * sizeof(unsigned);   // 69632 B
        cudaFuncSetAttribute(flash_tc_kernel,
                             cudaFuncAttributeMaxDynamicSharedMemorySize, (int)smem);
        dim3 grid(S_LEN / FBQ, NH);
        flash_tc_kernel<<<grid, FTHREADS, smem>>>(pq, pkh, pkl, pvh, pvl, pah, pal);
    }

    // O projection
    {
        dim3 grid(HIDDEN / BN, S_LEN / BM);
        gemm_o_kernel<<<grid, 256, gsmem>>>(pah, pal, o_qweight, o_scales, o_qzeros, out);
    }
}

// round 13
// speedup vs baseline: 1.0130x; 1.0130x over previous
#include <cuda_runtime.h>
#include <cuda_bf16.h>
#include <math.h>

// Problem constants
#define S_LEN 2048
#define HIDDEN 2560
#define NH 32
#define NKV 8
#define HD 128
#define QDIM (NH*HD)    // 4096
#define KVDIM (NKV*HD)  // 1024
#define GS 128

// -------- scratch (static device arrays; no allocation allowed) --------
__device__ float g_q[S_LEN * QDIM];            // Q fp32 (roped in-place)
__device__ float g_k[S_LEN * KVDIM];           // K fp32 (pre-rope)
__device__ float g_v[S_LEN * KVDIM];           // V fp32
__device__ __nv_bfloat16 g_xh[S_LEN * HIDDEN], g_xl[S_LEN * HIDDEN];
__device__ __nv_bfloat16 g_kh[S_LEN * KVDIM], g_kl[S_LEN * KVDIM];
__device__ __nv_bfloat16 g_vh[S_LEN * KVDIM], g_vl[S_LEN * KVDIM];
__device__ __nv_bfloat16 g_ah[S_LEN * QDIM],  g_al[S_LEN * QDIM];

// ======================================================================
// helpers
// ======================================================================
__device__ __forceinline__ void split2(float f0, float f1,
                                       unsigned &hi, unsigned &lo) {
    __nv_bfloat16 h0 = __float2bfloat16(f0);
    __nv_bfloat16 h1 = __float2bfloat16(f1);
    __nv_bfloat16 l0 = __float2bfloat16(f0 - __bfloat162float(h0));
    __nv_bfloat16 l1 = __float2bfloat16(f1 - __bfloat162float(h1));
    hi = (unsigned)__bfloat16_as_ushort(h0) |
         ((unsigned)__bfloat16_as_ushort(h1) << 16);
    lo = (unsigned)__bfloat16_as_ushort(l0) |
         ((unsigned)__bfloat16_as_ushort(l1) << 16);
}

__device__ __forceinline__ unsigned pack2(float f0, float f1) {
    return (unsigned)__bfloat16_as_ushort(__float2bfloat16(f0)) |
           ((unsigned)__bfloat16_as_ushort(__float2bfloat16(f1)) << 16);
}

__device__ __forceinline__ void mma_bf16(float c[4],
                                         unsigned a0, unsigned a1, unsigned a2, unsigned a3,
                                         unsigned b0, unsigned b1) {
    asm volatile(
        "mma.sync.aligned.m16n8k16.row.col.f32.bf16.bf16.f32 "
        "{%0,%1,%2,%3}, {%4,%5,%6,%7}, {%8,%9}, {%0,%1,%2,%3};"
        : "+f"(c[0]), "+f"(c[1]), "+f"(c[2]), "+f"(c[3])
        : "r"(a0), "r"(a1), "r"(a2), "r"(a3), "r"(b0), "r"(b1));
}

__device__ __forceinline__ void ldsm_x2_trans(unsigned &r0, unsigned &r1, unsigned addr) {
    asm volatile("ldmatrix.sync.aligned.m8n8.x2.trans.shared.b16 {%0,%1}, [%2];"
                 : "=r"(r0), "=r"(r1) : "r"(addr));
}

__device__ __forceinline__ unsigned smem_u32(const void* p) {
    return (unsigned)__cvta_generic_to_shared(p);
}

__device__ __forceinline__ void cp_async16(unsigned dst, const void* src) {
    asm volatile("cp.async.cg.shared.global [%0], [%1], 16;" :: "r"(dst), "l"(src));
}
#define CP_COMMIT() asm volatile("cp.async.commit_group;" ::: "memory")
#define CP_WAIT0()  asm volatile("cp.async.wait_group 0;" ::: "memory")
#define CP_WAIT1()  asm volatile("cp.async.wait_group 1;" ::: "memory")

// ======================================================================
// presplit: x fp32 -> bf16 hi/lo planes
// ======================================================================
__global__ __launch_bounds__(256)
void presplit_kernel(const float* __restrict__ x,
                     __nv_bfloat16* __restrict__ xh,
                     __nv_bfloat16* __restrict__ xl)
{
    int i = blockIdx.x * 256 + threadIdx.x;
    float2 v = ((const float2*)x)[i];
    unsigned h, l;
    split2(v.x, v.y, h, l);
    ((unsigned*)xh)[i] = h;
    ((unsigned*)xl)[i] = l;
}

// ======================================================================
// Dequant GEMM core (validated R8): presplit A + exact-int4 B + scale fold
// ======================================================================
#define BM 128
#define BN 128
#define BK 32
#define GST 20
#define GPL (128 * GST)
#define GBUF (3 * GPL)

__device__ __forceinline__ void gemm_core(
    const __nv_bfloat16* __restrict__ Ahp,
    const __nv_bfloat16* __restrict__ Alp,
    const int*   __restrict__ qw,
    const float* __restrict__ sc,
    const int*   __restrict__ qz,
    const float* __restrict__ bias,
    float* __restrict__ C,
    int N, int K, int bm, int bn, unsigned* gsm)
{
    unsigned sbase = smem_u32(gsm);

    int tid  = threadIdx.x;
    int lane = tid & 31;
    int warp = tid >> 5;
    int warp_m = warp & 1;
    int warp_n = warp >> 1;
    int t = lane & 3;
    int g = lane >> 2;

    int am[2], ach[2];
#pragma unroll
    for (int i = 0; i < 2; i++) {
        int c = tid + i * 256;
        am[i]  = c >> 2;
        ach[i] = c & 3;
    }
    int n_loc = tid & 127;
    int kp0   = (tid >> 7) << 1;

    int scol[4];
#pragma unroll
    for (int ni = 0; ni < 4; ni++)
        scol[ni] = bn + warp_n * 32 + ni * 8 + (t << 1);

    float acc[4][4][4];
#pragma unroll
    for (int mi = 0; mi < 4; mi++)
#pragma unroll
        for (int ni = 0; ni < 4; ni++)
#pragma unroll
            for (int r = 0; r < 4; r++) acc[mi][ni][r] = 0.f;

    float sreg[4][2];
    unsigned bw[2];
    float bz;

    int T = K / BK;

    {
        unsigned b0 = sbase;
#pragma unroll
        for (int i = 0; i < 2; i++) {
            const __nv_bfloat16* sh = Ahp + (size_t)(bm + am[i]) * K + ach[i] * 8;
            const __nv_bfloat16* sl = Alp + (size_t)(bm + am[i]) * K + ach[i] * 8;
            unsigned d = (unsigned)(am[i] * GST + ach[i] * 4) * 4;
            cp_async16(b0 + d, sh);
            cp_async16(b0 + GPL * 4 + d, sl);
        }
        CP_COMMIT();
        const int* qp = qw + (size_t)kp0 * N + bn + n_loc;
        bw[0] = (unsigned)qp[0];
        bw[1] = (unsigned)qp[N];
        bz = (float)qz[bn + n_loc];
        unsigned* Bs = gsm + 2 * GPL;
#pragma unroll
        for (int i = 0; i < 2; i++) {
            unsigned q = bw[i];
            int kpb = (kp0 + i) * 4;
#pragma unroll
            for (int j = 0; j < 4; j++)
                Bs[n_loc * GST + kpb + j] =
                    pack2((float)((q >> (8 * j)) & 15u) - bz,
                          (float)((q >> (8 * j + 4)) & 15u) - bz);
        }
        if (T > 1) {
            const int* qp1 = qw + (size_t)(4 + kp0) * N + bn + n_loc;
            bw[0] = (unsigned)qp1[0];
            bw[1] = (unsigned)qp1[N];
            bz = (float)qz[(size_t)(BK >> 7) * N + bn + n_loc];
        }
        CP_WAIT0();
        __syncthreads();
    }

    for (int it = 0; it < T; it++) {
        int k0 = it * BK;
        int b = it & 1;
        unsigned* base = gsm + b * GBUF;
        bool hasNext = (it + 1 < T);

        if (hasNext) {
            int kn = k0 + BK;
            unsigned nb = sbase + ((b ^ 1) * GBUF) * 4;
#pragma unroll
            for (int i = 0; i < 2; i++) {
                const __nv_bfloat16* sh = Ahp + (size_t)(bm + am[i]) * K + kn + ach[i] * 8;
                const __nv_bfloat16* sl = Alp + (size_t)(bm + am[i]) * K + kn + ach[i] * 8;
                unsigned d = (unsigned)(am[i] * GST + ach[i] * 4) * 4;
                cp_async16(nb + d, sh);
                cp_async16(nb + GPL * 4 + d, sl);
            }
            CP_COMMIT();
            unsigned* nBs = gsm + (b ^ 1) * GBUF + 2 * GPL;
#pragma unroll
            for (int i = 0; i < 2; i++) {
                unsigned q = bw[i];
                int kpb = (kp0 + i) * 4;
#pragma unroll
                for (int j = 0; j < 4; j++)
                    nBs[n_loc * GST + kpb + j] =
                        pack2((float)((q >> (8 * j)) & 15u) - bz,
                              (float)((q >> (8 * j + 4)) & 15u) - bz);
            }
            if (it + 2 < T) {
                int kn2 = k0 + 2 * BK;
                const int* qp = qw + (size_t)((kn2 >> 3) + kp0) * N + bn + n_loc;
                bw[0] = (unsigned)qp[0];
                bw[1] = (unsigned)qp[N];
                bz = (float)qz[(size_t)(kn2 >> 7) * N + bn + n_loc];
            }
        }

        if ((k0 & 127) == 0) {
            int grp = k0 >> 7;
#pragma unroll
            for (int ni = 0; ni < 4; ni++) {
                sreg[ni][0] = sc[(size_t)grp * N + scol[ni]];
                sreg[ni][1] = sc[(size_t)grp * N + scol[ni] + 1];
            }
        }

        const unsigned* AsH = base;
        const unsigned* AsL = base + GPL;
        const unsigned* Bs  = base + 2 * GPL;
        unsigned ah[2][4][4], al[2][4][4], bh[2][4][2];
#pragma unroll
        for (int ks = 0; ks < 2; ks++) {
            int kpb = ks * 8;
#pragma unroll
            for (int mi = 0; mi < 4; mi++) {
                int r = warp_m * 64 + mi * 16 + g;
                ah[ks][mi][0] = AsH[r * GST + kpb + t];
                ah[ks][mi][1] = AsH[(r + 8) * GST + kpb + t];
                ah[ks][mi][2] = AsH[r * GST + kpb + t + 4];
                ah[ks][mi][3] = AsH[(r + 8) * GST + kpb + t + 4];
                al[ks][mi][0] = AsL[r * GST + kpb + t];
                al[ks][mi][1] = AsL[(r + 8) * GST + kpb + t];
                al[ks][mi][2] = AsL[r * GST + kpb + t + 4];
                al[ks][mi][3] = AsL[(r + 8) * GST + kpb + t + 4];
            }
#pragma unroll
            for (int ni = 0; ni < 4; ni++) {
                int c = warp_n * 32 + ni * 8 + g;
                bh[ks][ni][0] = Bs[c * GST + kpb + t];
                bh[ks][ni][1] = Bs[c * GST + kpb + t + 4];
            }
        }

        float tmp[2][4];
#pragma unroll
        for (int u = 0; u < 16; u++) {
            int mi = u >> 2, ni = u & 3, pb = u & 1;
            tmp[pb][0] = 0.f; tmp[pb][1] = 0.f;
            tmp[pb][2] = 0.f; tmp[pb][3] = 0.f;
            mma_bf16(tmp[pb], ah[0][mi][0], ah[0][mi][1], ah[0][mi][2], ah[0][mi][3],
                     bh[0][ni][0], bh[0][ni][1]);
            mma_bf16(tmp[pb], al[0][mi][0], al[0][mi][1], al[0][mi][2], al[0][mi][3],
                     bh[0][ni][0], bh[0][ni][1]);
            mma_bf16(tmp[pb], ah[1][mi][0], ah[1][mi][1], ah[1][mi][2], ah[1][mi][3],
                     bh[1][ni][0], bh[1][ni][1]);
            mma_bf16(tmp[pb], al[1][mi][0], al[1][mi][1], al[1][mi][2], al[1][mi][3],
                     bh[1][ni][0], bh[1][ni][1]);
            if (u > 0) {
                int v = u - 1, vm = v >> 2, vn = v & 3, vb = v & 1;
                acc[vm][vn][0] += tmp[vb][0] * sreg[vn][0];
                acc[vm][vn][1] += tmp[vb][1] * sreg[vn][1];
                acc[vm][vn][2] += tmp[vb][2] * sreg[vn][0];
                acc[vm][vn][3] += tmp[vb][3] * sreg[vn][1];
            }
        }
        acc[3][3][0] += tmp[1][0] * sreg[3][0];
        acc[3][3][1] += tmp[1][1] * sreg[3][1];
        acc[3][3][2] += tmp[1][2] * sreg[3][0];
        acc[3][3][3] += tmp[1][3] * sreg[3][1];

        if (hasNext) CP_WAIT0();
        __syncthreads();
    }

#pragma unroll
    for (int ni = 0; ni < 4; ni++) {
        int n = scol[ni];
        float b0 = 0.f, b1 = 0.f;
        if (bias) { b0 = bias[n]; b1 = bias[n + 1]; }
#pragma unroll
        for (int mi = 0; mi < 4; mi++) {
            int m = bm + warp_m * 64 + mi * 16 + g;
            float2 v0 = make_float2(acc[mi][ni][0] + b0, acc[mi][ni][1] + b1);
            float2 v1 = make_float2(acc[mi][ni][2] + b0, acc[mi][ni][3] + b1);
            *(float2*)(C + (size_t)m * N + n) = v0;
            *(float2*)(C + (size_t)(m + 8) * N + n) = v1;
        }
    }
}

__global__ __launch_bounds__(256, 2)
void gemm_qkv_kernel(const __nv_bfloat16* __restrict__ xh,
                     const __nv_bfloat16* __restrict__ xl,
    const int* __restrict__ qwq, const float* __restrict__ scq,
    const int* __restrict__ qzq, const float* __restrict__ bq,
    const int* __restrict__ qwk, const float* __restrict__ sck,
    const int* __restrict__ qzk, const float* __restrict__ bk,
    const int* __restrict__ qwv, const float* __restrict__ scv,
    const int* __restrict__ qzv, const float* __restrict__ bv,
    float* __restrict__ Cq, float* __restrict__ Ck, float* __restrict__ Cv)
{
    extern __shared__ unsigned gsm[];
    int bt = blockIdx.x;
    int bm = blockIdx.y * BM;
    const int* qw; const float* sc; const int* qz; const float* bias;
    float* C; int N; int bn;
    if (bt < 32)      { qw = qwq; sc = scq; qz = qzq; bias = bq; C = Cq; N = QDIM;  bn = bt * BN; }
    else if (bt < 40) { qw = qwk; sc = sck; qz = qzk; bias = bk; C = Ck; N = KVDIM; bn = (bt - 32) * BN; }
    else              { qw = qwv; sc = scv; qz = qzv; bias = bv; C = Cv; N = KVDIM; bn = (bt - 40) * BN; }
    gemm_core(xh, xl, qw, sc, qz, bias, C, N, HIDDEN, bm, bn, gsm);
}

__global__ __launch_bounds__(256, 2)
void gemm_o_kernel(const __nv_bfloat16* __restrict__ ah,
                   const __nv_bfloat16* __restrict__ al,
                   const int* __restrict__ qw, const float* __restrict__ sc,
                   const int* __restrict__ qz, float* __restrict__ C)
{
    extern __shared__ unsigned gsm[];
    gemm_core(ah, al, qw, sc, qz, nullptr, C, HIDDEN, QDIM,
              blockIdx.y * BM, blockIdx.x * BN, gsm);
}

// ======================================================================
// RoPE + split (unchanged)
// ======================================================================
__global__ __launch_bounds__(256)
void rope_split_kernel(float* __restrict__ Qb,
                       const float* __restrict__ Kf,
                       const float* __restrict__ Vf,
                       __nv_bfloat16* __restrict__ Kh, __nv_bfloat16* __restrict__ Kl,
                       __nv_bfloat16* __restrict__ Vh, __nv_bfloat16* __restrict__ Vl,
                       const float* __restrict__ cosb,
                       const float* __restrict__ sinb)
{
    int s = blockIdx.y;
    int h = blockIdx.x * 4 + (threadIdx.x >> 6);
    int d = threadIdx.x & 63;

    if (h < NH) {
        float c1 = cosb[s * HD + d],     s1 = sinb[s * HD + d];
        float c2 = cosb[s * HD + d + 64], s2 = sinb[s * HD + d + 64];
        float* base = Qb + (size_t)s * QDIM + h * HD;
        float x1 = base[d], x2 = base[d + 64];
        base[d]      = x1 * c1 - x2 * s1;
        base[d + 64] = x2 * c2 + x1 * s2;
    } else if (h < NH + NKV) {
        int kh = h - NH;
        float c1 = cosb[s * HD + d],     s1 = sinb[s * HD + d];
        float c2 = cosb[s * HD + d + 64], s2 = sinb[s * HD + d + 64];
        const float* base = Kf + (size_t)s * KVDIM + kh * HD;
        float x1 = base[d], x2 = base[d + 64];
        float y1 = x1 * c1 - x2 * s1;
        float y2 = x2 * c2 + x1 * s2;
        size_t o = (size_t)s * KVDIM + kh * HD + d;
        __nv_bfloat16 h1 = __float2bfloat16(y1);
        __nv_bfloat16 h2 = __float2bfloat16(y2);
        Kh[o] = h1;       Kl[o] = __float2bfloat16(y1 - __bfloat162float(h1));
        Kh[o + 64] = h2;  Kl[o + 64] = __float2bfloat16(y2 - __bfloat162float(h2));
    } else {
        int vh = h - NH - NKV;
        const float* base = Vf + (size_t)s * KVDIM + vh * HD;
        float x1 = base[d], x2 = base[d + 64];
        size_t o = (size_t)s * KVDIM + vh * HD + d;
        __nv_bfloat16 h1 = __float2bfloat16(x1);
        __nv_bfloat16 h2 = __float2bfloat16(x2);
        Vh[o] = h1;       Vl[o] = __float2bfloat16(x1 - __bfloat162float(h1));
        Vh[o + 64] = h2;  Vl[o + 64] = __float2bfloat16(x2 - __bfloat162float(h2));
    }
}

// ======================================================================
// bf16x3 flash attention: FBQ=64, 128-thread CTAs, 2 CTAs/SM.
// K/V loads in separate cp.async groups, software-pipelined:
//   V(t) loads during scores(t);  K(t+1) loads during softmax+PV(t).
// Chunk mapping (R10-proven): 1024 chunks/plane = 64 rows x 16 chunks;
//   idx = tid + i*128 (i<8), r = idx>>4, ch = idx&15.
// ======================================================================
#define FBQ 64
#define FBK 64
#define FTHREADS 128
#define KVW 68
#define FPLANE (FBK * KVW)

__global__ __launch_bounds__(FTHREADS, 2)
void flash_tc_kernel(const float* __restrict__ Q,
                     const __nv_bfloat16* __restrict__ Kh,
                     const __nv_bfloat16* __restrict__ Kl,
                     const __nv_bfloat16* __restrict__ Vh,
                     const __nv_bfloat16* __restrict__ Vl,
                     __nv_bfloat16* __restrict__ Oh,
                     __nv_bfloat16* __restrict__ Ol)
{
    extern __shared__ unsigned fsm[];
    unsigned (*KsH)[KVW] = (unsigned(*)[KVW])(fsm);
    unsigned (*KsL)[KVW] = (unsigned(*)[KVW])(fsm + FPLANE);
    unsigned (*VsH)[KVW] = (unsigned(*)[KVW])(fsm + 2 * FPLANE);
    unsigned (*VsL)[KVW] = (unsigned(*)[KVW])(fsm + 3 * FPLANE);

    int h = blockIdx.y;
    int qt = gridDim.x - 1 - blockIdx.x;   // largest q-tile first
    int q0 = qt * FBQ;
    int kvh = h >> 2;
    int tid = threadIdx.x, lane = tid & 31, warp = tid >> 5;
    int t = lane & 3, g = lane >> 2;

    unsigned kbH = smem_u32(KsH), kbL = smem_u32(KsL);
    unsigned vbH = smem_u32(VsH), vbL = smem_u32(VsL);

    const __nv_bfloat16* Khb = Kh + kvh * HD;
    const __nv_bfloat16* Klb = Kl + kvh * HD;
    const __nv_bfloat16* Vhb = Vh + kvh * HD;
    const __nv_bfloat16* Vlb = Vl + kvh * HD;

    // ---- Q fragments, scale folded, split hi/lo (regs) ----
    unsigned qh[8][4], ql[8][4];
    {
        const float sc = 0.08838834764831845f;
        int r0 = q0 + warp * 16 + g;
        const float* p0 = Q + (size_t)r0 * QDIM + h * HD;
        const float* p1 = p0 + 8 * QDIM;
#pragma unroll
        for (int ks = 0; ks < 8; ks++) {
            int d = ks * 16 + 2 * t;
            float2 a0 = *(const float2*)(p0 + d);
            float2 a1 = *(const float2*)(p1 + d);
            float2 a2 = *(const float2*)(p0 + d + 8);
            float2 a3 = *(const float2*)(p1 + d + 8);
            split2(a0.x * sc, a0.y * sc, qh[ks][0], ql[ks][0]);
            split2(a1.x * sc, a1.y * sc, qh[ks][1], ql[ks][1]);
            split2(a2.x * sc, a2.y * sc, qh[ks][2], ql[ks][2]);
            split2(a3.x * sc, a3.y * sc, qh[ks][3], ql[ks][3]);
        }
    }

    float m0 = -INFINITY, m1 = -INFINITY, l0s = 0.f, l1s = 0.f;
    float o_acc[16][4];
#pragma unroll
    for (int nj = 0; nj < 16; nj++)
#pragma unroll
        for (int r = 0; r < 4; r++) o_acc[nj][r] = 0.f;

    int ntiles = qt + 1;

    // ---- prologue: issue K0 group, then V0 group ----
#pragma unroll
    for (int i = 0; i < 8; i++) {
        int idx = tid + i * FTHREADS;
        int r = idx >> 4;              // token 0..63
        int ch = idx & 15;             // 16B chunk (8 bf16)
        size_t off = (size_t)r * KVDIM + ch * 8;
        unsigned d = (unsigned)(r * KVW + ch * 4) * 4;
        cp_async16(kbH + d, Khb + off);
        cp_async16(kbL + d, Klb + off);
    }
    CP_COMMIT();
#pragma unroll
    for (int i = 0; i < 8; i++) {
        int idx = tid + i * FTHREADS;
        int r = idx >> 4;
        int ch = idx & 15;
        size_t off = (size_t)r * KVDIM + ch * 8;
        unsigned d = (unsigned)(r * KVW + ch * 4) * 4;
        cp_async16(vbH + d, Vhb + off);
        cp_async16(vbL + d, Vlb + off);
    }
    CP_COMMIT();

    for (int tt = 0; tt < ntiles; tt++) {
        bool hasNext = (tt + 1 < ntiles);

        // ---- K(tt) ready (V(tt) may still be in flight) ----
        CP_WAIT1();
        __syncthreads();

        // ---- scores S = Q K^T (bf16x3); V(tt) loads underneath ----
        float s[8][4];
#pragma unroll
        for (int ni = 0; ni < 8; ni++)
#pragma unroll
            for (int r = 0; r < 4; r++) s[ni][r] = 0.f;

#pragma unroll
        for (int ks = 0; ks < 8; ks++) {
            int w = ks * 8 + t;
#pragma unroll
            for (int ni = 0; ni < 8; ni++) {
                int col = ni * 8 + g;
                unsigned bh0 = KsH[col][w], bh1 = KsH[col][w + 4];
                unsigned bl0 = KsL[col][w], bl1 = KsL[col][w + 4];
                mma_bf16(s[ni], qh[ks][0], qh[ks][1], qh[ks][2], qh[ks][3], bh0, bh1);
                mma_bf16(s[ni], qh[ks][0], qh[ks][1], qh[ks][2], qh[ks][3], bl0, bl1);
                mma_bf16(s[ni], ql[ks][0], ql[ks][1], ql[ks][2], ql[ks][3], bh0, bh1);
            }
        }
        __syncthreads();   // all warps done reading K buffer

        // ---- issue K(tt+1) into K buffer; loads during softmax+PV ----
        if (hasNext) {
            int kb1 = (tt + 1) << 6;
#pragma unroll
            for (int i = 0; i < 8; i++) {
                int idx = tid + i * FTHREADS;
                int r = idx >> 4;
                int ch = idx & 15;
                size_t off = (size_t)(kb1 + r) * KVDIM + ch * 8;
                unsigned d = (unsigned)(r * KVW + ch * 4) * 4;
                cp_async16(kbH + d, Khb + off);
                cp_async16(kbL + d, Klb + off);
            }
            CP_COMMIT();
            CP_WAIT1();   // V(tt) done; K(tt+1) remains in flight
        } else {
            CP_WAIT0();   // V(tt) done
        }

        // ---- causal mask (diagonal tile only) ----
        int kb = tt << 6;
        if (kb + FBK > q0) {
            int r0 = q0 + warp * 16 + g, r1 = r0 + 8;
#pragma unroll
            for (int ni = 0; ni < 8; ni++) {
                int c0 = kb + ni * 8 + 2 * t, c1 = c0 + 1;
                if (c0 > r0) s[ni][0] = -INFINITY;
                if (c1 > r0) s[ni][1] = -INFINITY;
                if (c0 > r1) s[ni][2] = -INFINITY;
                if (c1 > r1) s[ni][3] = -INFINITY;
            }
        }

        // ---- online softmax ----
        float rm0 = -INFINITY, rm1 = -INFINITY;
#pragma unroll
        for (int ni = 0; ni < 8; ni++) {
            rm0 = fmaxf(rm0, fmaxf(s[ni][0], s[ni][1]));
            rm1 = fmaxf(rm1, fmaxf(s[ni][2], s[ni][3]));
        }
        rm0 = fmaxf(rm0, __shfl_xor_sync(0xffffffffu, rm0, 1));
        rm0 = fmaxf(rm0, __shfl_xor_sync(0xffffffffu, rm0, 2));
        rm1 = fmaxf(rm1, __shfl_xor_sync(0xffffffffu, rm1, 1));
        rm1 = fmaxf(rm1, __shfl_xor_sync(0xffffffffu, rm1, 2));
        float mn0 = fmaxf(m0, rm0), mn1 = fmaxf(m1, rm1);
        float cr0 = __expf(m0 - mn0), cr1 = __expf(m1 - mn1);
        m0 = mn0; m1 = mn1;
        float ps0 = 0.f, ps1 = 0.f;
#pragma unroll
        for (int ni = 0; ni < 8; ni++) {
            s[ni][0] = __expf(s[ni][0] - mn0);
            s[ni][1] = __expf(s[ni][1] - mn0);
            s[ni][2] = __expf(s[ni][2] - mn1);
            s[ni][3] = __expf(s[ni][3] - mn1);
            ps0 += s[ni][0] + s[ni][1];
            ps1 += s[ni][2] + s[ni][3];
        }
        ps0 += __shfl_xor_sync(0xffffffffu, ps0, 1);
        ps0 += __shfl_xor_sync(0xffffffffu, ps0, 2);
        ps1 += __shfl_xor_sync(0xffffffffu, ps1, 1);
        ps1 += __shfl_xor_sync(0xffffffffu, ps1, 2);
        l0s = l0s * cr0 + ps0;
        l1s = l1s * cr1 + ps1;
#pragma unroll
        for (int nj = 0; nj < 16; nj++) {
            o_acc[nj][0] *= cr0; o_acc[nj][1] *= cr0;
            o_acc[nj][2] *= cr1; o_acc[nj][3] *= cr1;
        }

        __syncthreads();   // V buffer fully loaded & visible to all warps

        // ---- O += P V (bf16x3); K(tt+1) loads underneath ----
#pragma unroll
        for (int ks2 = 0; ks2 < 4; ks2++) {
            unsigned ph[4], pl[4];
            split2(s[2 * ks2][0],     s[2 * ks2][1],     ph[0], pl[0]);
            split2(s[2 * ks2][2],     s[2 * ks2][3],     ph[1], pl[1]);
            split2(s[2 * ks2 + 1][0], s[2 * ks2 + 1][1], ph[2], pl[2]);
            split2(s[2 * ks2 + 1][2], s[2 * ks2 + 1][3], ph[3], pl[3]);
            unsigned rowb = (unsigned)(ks2 * 16 + (lane & 15)) * (KVW * 4);
#pragma unroll
            for (int nj = 0; nj < 16; nj++) {
                unsigned v0, v1, u0, u1;
                ldsm_x2_trans(v0, v1, vbH + rowb + nj * 16);
                ldsm_x2_trans(u0, u1, vbL + rowb + nj * 16);
                mma_bf16(o_acc[nj], ph[0], ph[1], ph[2], ph[3], v0, v1);
                mma_bf16(o_acc[nj], ph[0], ph[1], ph[2], ph[3], u0, u1);
                mma_bf16(o_acc[nj], pl[0], pl[1], pl[2], pl[3], v0, v1);
            }
        }
        __syncthreads();   // all warps done reading V buffer

        // ---- issue V(tt+1); loads during next scores ----
        if (hasNext) {
            int kb1 = (tt + 1) << 6;
#pragma unroll
            for (int i = 0; i < 8; i++) {
                int idx = tid + i * FTHREADS;
                int r = idx >> 4;
                int ch = idx & 15;
                size_t off = (size_t)(kb1 + r) * KVDIM + ch * 8;
                unsigned d = (unsigned)(r * KVW + ch * 4) * 4;
                cp_async16(vbH + d, Vhb + off);
                cp_async16(vbL + d, Vlb + off);
            }
            CP_COMMIT();
        }
    }

    // ---- epilogue: write bf16 hi/lo planes ----
    float inv0 = 1.f / l0s, inv1 = 1.f / l1s;
    int r0 = q0 + warp * 16 + g;
    size_t b0 = (size_t)r0 * QDIM + h * HD;
    size_t b1 = b0 + 8 * (size_t)QDIM;
#pragma unroll
    for (int nj = 0; nj < 16; nj++) {
        int d = nj * 8 + 2 * t;
        unsigned hh, ll;
        split2(o_acc[nj][0] * inv0, o_acc[nj][1] * inv0, hh, ll);
        *(unsigned*)(Oh + b0 + d) = hh;
        *(unsigned*)(Ol + b0 + d) = ll;
        split2(o_acc[nj][2] * inv1, o_acc[nj][3] * inv1, hh, ll);
        *(unsigned*)(Oh + b1 + d) = hh;
        *(unsigned*)(Ol + b1 + d) = ll;
    }
}

// ======================================================================
// Launch
// ======================================================================
extern "C" void kernel_launch(void* const* d_in, const int* in_sizes, int n_in,
                              void* d_out, int out_size)
{
    const float* x        = (const float*)d_in[0];
    const float* cosb     = (const float*)d_in[1];
    const float* sinb     = (const float*)d_in[2];
    const float* q_scales = (const float*)d_in[3];
    const float* q_bias   = (const float*)d_in[4];
    const float* k_scales = (const float*)d_in[5];
    const float* k_bias   = (const float*)d_in[6];
    const float* v_scales = (const float*)d_in[7];
    const float* v_bias   = (const float*)d_in[8];
    const float* o_scales = (const float*)d_in[9];
    const int* q_qweight  = (const int*)d_in[10];
    const int* q_qzeros   = (const int*)d_in[11];
    const int* k_qweight  = (const int*)d_in[12];
    const int* k_qzeros   = (const int*)d_in[13];
    const int* v_qweight  = (const int*)d_in[14];
    const int* v_qzeros   = (const int*)d_in[15];
    const int* o_qweight  = (const int*)d_in[16];
    const int* o_qzeros   = (const int*)d_in[17];
    float* out = (float*)d_out;

    float *pq, *pk, *pv;
    __nv_bfloat16 *pxh, *pxl, *pkh, *pkl, *pvh, *pvl, *pah, *pal;
    cudaGetSymbolAddress((void**)&pq, g_q);
    cudaGetSymbolAddress((void**)&pk, g_k);
    cudaGetSymbolAddress((void**)&pv, g_v);
    cudaGetSymbolAddress((void**)&pxh, g_xh);
    cudaGetSymbolAddress((void**)&pxl, g_xl);
    cudaGetSymbolAddress((void**)&pkh, g_kh);
    cudaGetSymbolAddress((void**)&pkl, g_kl);
    cudaGetSymbolAddress((void**)&pvh, g_vh);
    cudaGetSymbolAddress((void**)&pvl, g_vl);
    cudaGetSymbolAddress((void**)&pah, g_ah);
    cudaGetSymbolAddress((void**)&pal, g_al);

    size_t gsmem = (size_t)(2 * GBUF) * sizeof(unsigned);
    cudaFuncSetAttribute(gemm_qkv_kernel,
                         cudaFuncAttributeMaxDynamicSharedMemorySize, (int)gsmem);
    cudaFuncSetAttribute(gemm_o_kernel,
                         cudaFuncAttributeMaxDynamicSharedMemorySize, (int)gsmem);

    // presplit x
    presplit_kernel<<<(S_LEN * HIDDEN / 2) / 256, 256>>>(x, pxh, pxl);

    // fused QKV projection
    {
        dim3 grid(48, S_LEN / BM);
        gemm_qkv_kernel<<<grid, 256, gsmem>>>(
            pxh, pxl,
            q_qweight, q_scales, q_qzeros, q_bias,
            k_qweight, k_scales, k_qzeros, k_bias,
            v_qweight, v_scales, v_qzeros, v_bias,
            pq, pk, pv);
    }

    // RoPE (Q in-place) + K/V presplit
    {
        dim3 grid(12, S_LEN);
        rope_split_kernel<<<grid, 256>>>(pq, pk, pv, pkh, pkl, pvh, pvl, cosb, sinb);
    }

    // Flash attention (pipelined K/V loads, 2 CTAs/SM)
    {
        size_t smem = (size_t)(4 * FPLANE) * sizeof(unsigned);   // 69632 B
        cudaFuncSetAttribute(flash_tc_kernel,
                             cudaFuncAttributeMaxDynamicSharedMemorySize, (int)smem);
        dim3 grid(S_LEN / FBQ, NH);
        flash_tc_kernel<<<grid, FTHREADS, smem>>>(pq, pkh, pkl, pvh, pvl, pah, pal);
    }

    // O projection
    {
        dim3 grid(HIDDEN / BN, S_LEN / BM);
        gemm_o_kernel<<<grid, 256, gsmem>>>(pah, pal, o_qweight, o_scales, o_qzeros, out);
    }
}

// round 15
// speedup vs baseline: 1.0899x; 1.0758x over previous
#include <cuda_runtime.h>
#include <cuda_bf16.h>
#include <math.h>

// Problem constants
#define S_LEN 2048
#define HIDDEN 2560
#define NH 32
#define NKV 8
#define HD 128
#define QDIM (NH*HD)    // 4096
#define KVDIM (NKV*HD)  // 1024
#define GS 128
#define OSPLIT 4        // split-K factor for O projection

// -------- scratch (static device arrays; no allocation allowed) --------
__device__ float g_q[S_LEN * QDIM];            // Q fp32 (roped in-place)
__device__ float g_k[S_LEN * KVDIM];           // K fp32 (pre-rope)
__device__ float g_v[S_LEN * KVDIM];           // V fp32
__device__ __nv_bfloat16 g_xh[S_LEN * HIDDEN], g_xl[S_LEN * HIDDEN];
__device__ __nv_bfloat16 g_kh[S_LEN * KVDIM], g_kl[S_LEN * KVDIM];
__device__ __nv_bfloat16 g_vh[S_LEN * KVDIM], g_vl[S_LEN * KVDIM];
__device__ __nv_bfloat16 g_ah[S_LEN * QDIM],  g_al[S_LEN * QDIM];

// ======================================================================
// helpers
// ======================================================================
__device__ __forceinline__ void split2(float f0, float f1,
                                       unsigned &hi, unsigned &lo) {
    __nv_bfloat16 h0 = __float2bfloat16(f0);
    __nv_bfloat16 h1 = __float2bfloat16(f1);
    __nv_bfloat16 l0 = __float2bfloat16(f0 - __bfloat162float(h0));
    __nv_bfloat16 l1 = __float2bfloat16(f1 - __bfloat162float(h1));
    hi = (unsigned)__bfloat16_as_ushort(h0) |
         ((unsigned)__bfloat16_as_ushort(h1) << 16);
    lo = (unsigned)__bfloat16_as_ushort(l0) |
         ((unsigned)__bfloat16_as_ushort(l1) << 16);
}

__device__ __forceinline__ unsigned pack2(float f0, float f1) {
    return (unsigned)__bfloat16_as_ushort(__float2bfloat16(f0)) |
           ((unsigned)__bfloat16_as_ushort(__float2bfloat16(f1)) << 16);
}

__device__ __forceinline__ void mma_bf16(float c[4],
                                         unsigned a0, unsigned a1, unsigned a2, unsigned a3,
                                         unsigned b0, unsigned b1) {
    asm volatile(
        "mma.sync.aligned.m16n8k16.row.col.f32.bf16.bf16.f32 "
        "{%0,%1,%2,%3}, {%4,%5,%6,%7}, {%8,%9}, {%0,%1,%2,%3};"
        : "+f"(c[0]), "+f"(c[1]), "+f"(c[2]), "+f"(c[3])
        : "r"(a0), "r"(a1), "r"(a2), "r"(a3), "r"(b0), "r"(b1));
}

__device__ __forceinline__ void ldsm_x2_trans(unsigned &r0, unsigned &r1, unsigned addr) {
    asm volatile("ldmatrix.sync.aligned.m8n8.x2.trans.shared.b16 {%0,%1}, [%2];"
                 : "=r"(r0), "=r"(r1) : "r"(addr));
}

__device__ __forceinline__ unsigned smem_u32(const void* p) {
    return (unsigned)__cvta_generic_to_shared(p);
}

__device__ __forceinline__ void cp_async16(unsigned dst, const void* src) {
    asm volatile("cp.async.cg.shared.global [%0], [%1], 16;" :: "r"(dst), "l"(src));
}
#define CP_COMMIT() asm volatile("cp.async.commit_group;" ::: "memory")
#define CP_WAIT0()  asm volatile("cp.async.wait_group 0;" ::: "memory")
#define CP_WAIT1()  asm volatile("cp.async.wait_group 1;" ::: "memory")

// ======================================================================
// presplit: x fp32 -> bf16 hi/lo planes
// ======================================================================
__global__ __launch_bounds__(256)
void presplit_kernel(const float* __restrict__ x,
                     __nv_bfloat16* __restrict__ xh,
                     __nv_bfloat16* __restrict__ xl)
{
    int i = blockIdx.x * 256 + threadIdx.x;
    float2 v = ((const float2*)x)[i];
    unsigned h, l;
    split2(v.x, v.y, h, l);
    ((unsigned*)xh)[i] = h;
    ((unsigned*)xl)[i] = l;
}

// ======================================================================
// zero-init for atomic split-K output
// ======================================================================
__global__ __launch_bounds__(256)
void zero_kernel(float* __restrict__ p)
{
    int i = blockIdx.x * 256 + threadIdx.x;
    ((float4*)p)[i] = make_float4(0.f, 0.f, 0.f, 0.f);
}

// ======================================================================
// Dequant GEMM core (validated R8) + Kstride/Klen + atomic epilogue.
// presplit A (cp.async) + exact-int4 B + per-group scale fold.
// BM=128 BN=128 BK=32, 8 warps (2x4), warp tile 64x32, double-buffered.
// Callers pre-offset A/qw/sc/qz pointers for split-K slices.
// ======================================================================
#define BM 128
#define BN 128
#define BK 32
#define GST 20
#define GPL (128 * GST)
#define GBUF (3 * GPL)

__device__ __forceinline__ void gemm_core(
    const __nv_bfloat16* __restrict__ Ahp,
    const __nv_bfloat16* __restrict__ Alp,
    const int*   __restrict__ qw,
    const float* __restrict__ sc,
    const int*   __restrict__ qz,
    const float* __restrict__ bias,
    float* __restrict__ C,
    int N, int Kstride, int Klen, int bm, int bn, bool atomic, unsigned* gsm)
{
    unsigned sbase = smem_u32(gsm);

    int tid  = threadIdx.x;
    int lane = tid & 31;
    int warp = tid >> 5;
    int warp_m = warp & 1;
    int warp_n = warp >> 1;
    int t = lane & 3;
    int g = lane >> 2;

    int am[2], ach[2];
#pragma unroll
    for (int i = 0; i < 2; i++) {
        int c = tid + i * 256;
        am[i]  = c >> 2;
        ach[i] = c & 3;
    }
    int n_loc = tid & 127;
    int kp0   = (tid >> 7) << 1;

    int scol[4];
#pragma unroll
    for (int ni = 0; ni < 4; ni++)
        scol[ni] = bn + warp_n * 32 + ni * 8 + (t << 1);

    float acc[4][4][4];
#pragma unroll
    for (int mi = 0; mi < 4; mi++)
#pragma unroll
        for (int ni = 0; ni < 4; ni++)
#pragma unroll
            for (int r = 0; r < 4; r++) acc[mi][ni][r] = 0.f;

    float sreg[4][2];
    unsigned bw[2];
    float bz;

    int T = Klen / BK;

    {
        unsigned b0 = sbase;
#pragma unroll
        for (int i = 0; i < 2; i++) {
            const __nv_bfloat16* sh = Ahp + (size_t)(bm + am[i]) * Kstride + ach[i] * 8;
            const __nv_bfloat16* sl = Alp + (size_t)(bm + am[i]) * Kstride + ach[i] * 8;
            unsigned d = (unsigned)(am[i] * GST + ach[i] * 4) * 4;
            cp_async16(b0 + d, sh);
            cp_async16(b0 + GPL * 4 + d, sl);
        }
        CP_COMMIT();
        const int* qp = qw + (size_t)kp0 * N + bn + n_loc;
        bw[0] = (unsigned)qp[0];
        bw[1] = (unsigned)qp[N];
        bz = (float)qz[bn + n_loc];
        unsigned* Bs = gsm + 2 * GPL;
#pragma unroll
        for (int i = 0; i < 2; i++) {
            unsigned q = bw[i];
            int kpb = (kp0 + i) * 4;
#pragma unroll
            for (int j = 0; j < 4; j++)
                Bs[n_loc * GST + kpb + j] =
                    pack2((float)((q >> (8 * j)) & 15u) - bz,
                          (float)((q >> (8 * j + 4)) & 15u) - bz);
        }
        if (T > 1) {
            const int* qp1 = qw + (size_t)(4 + kp0) * N + bn + n_loc;
            bw[0] = (unsigned)qp1[0];
            bw[1] = (unsigned)qp1[N];
            bz = (float)qz[(size_t)(BK >> 7) * N + bn + n_loc];
        }
        CP_WAIT0();
        __syncthreads();
    }

    for (int it = 0; it < T; it++) {
        int k0 = it * BK;
        int b = it & 1;
        unsigned* base = gsm + b * GBUF;
        bool hasNext = (it + 1 < T);

        if (hasNext) {
            int kn = k0 + BK;
            unsigned nb = sbase + ((b ^ 1) * GBUF) * 4;
#pragma unroll
            for (int i = 0; i < 2; i++) {
                const __nv_bfloat16* sh = Ahp + (size_t)(bm + am[i]) * Kstride + kn + ach[i] * 8;
                const __nv_bfloat16* sl = Alp + (size_t)(bm + am[i]) * Kstride + kn + ach[i] * 8;
                unsigned d = (unsigned)(am[i] * GST + ach[i] * 4) * 4;
                cp_async16(nb + d, sh);
                cp_async16(nb + GPL * 4 + d, sl);
            }
            CP_COMMIT();
            unsigned* nBs = gsm + (b ^ 1) * GBUF + 2 * GPL;
#pragma unroll
            for (int i = 0; i < 2; i++) {
                unsigned q = bw[i];
                int kpb = (kp0 + i) * 4;
#pragma unroll
                for (int j = 0; j < 4; j++)
                    nBs[n_loc * GST + kpb + j] =
                        pack2((float)((q >> (8 * j)) & 15u) - bz,
                              (float)((q >> (8 * j + 4)) & 15u) - bz);
            }
            if (it + 2 < T) {
                int kn2 = k0 + 2 * BK;
                const int* qp = qw + (size_t)((kn2 >> 3) + kp0) * N + bn + n_loc;
                bw[0] = (unsigned)qp[0];
                bw[1] = (unsigned)qp[N];
                bz = (float)qz[(size_t)(kn2 >> 7) * N + bn + n_loc];
            }
        }

        if ((k0 & 127) == 0) {
            int grp = k0 >> 7;
#pragma unroll
            for (int ni = 0; ni < 4; ni++) {
                sreg[ni][0] = sc[(size_t)grp * N + scol[ni]];
                sreg[ni][1] = sc[(size_t)grp * N + scol[ni] + 1];
            }
        }

        const unsigned* AsH = base;
        const unsigned* AsL = base + GPL;
        const unsigned* Bs  = base + 2 * GPL;
        unsigned ah[2][4][4], al[2][4][4], bh[2][4][2];
#pragma unroll
        for (int ks = 0; ks < 2; ks++) {
            int kpb = ks * 8;
#pragma unroll
            for (int mi = 0; mi < 4; mi++) {
                int r = warp_m * 64 + mi * 16 + g;
                ah[ks][mi][0] = AsH[r * GST + kpb + t];
                ah[ks][mi][1] = AsH[(r + 8) * GST + kpb + t];
                ah[ks][mi][2] = AsH[r * GST + kpb + t + 4];
                ah[ks][mi][3] = AsH[(r + 8) * GST + kpb + t + 4];
                al[ks][mi][0] = AsL[r * GST + kpb + t];
                al[ks][mi][1] = AsL[(r + 8) * GST + kpb + t];
                al[ks][mi][2] = AsL[r * GST + kpb + t + 4];
                al[ks][mi][3] = AsL[(r + 8) * GST + kpb + t + 4];
            }
#pragma unroll
            for (int ni = 0; ni < 4; ni++) {
                int c = warp_n * 32 + ni * 8 + g;
                bh[ks][ni][0] = Bs[c * GST + kpb + t];
                bh[ks][ni][1] = Bs[c * GST + kpb + t + 4];
            }
        }

        float tmp[2][4];
#pragma unroll
        for (int u = 0; u < 16; u++) {
            int mi = u >> 2, ni = u & 3, pb = u & 1;
            tmp[pb][0] = 0.f; tmp[pb][1] = 0.f;
            tmp[pb][2] = 0.f; tmp[pb][3] = 0.f;
            mma_bf16(tmp[pb], ah[0][mi][0], ah[0][mi][1], ah[0][mi][2], ah[0][mi][3],
                     bh[0][ni][0], bh[0][ni][1]);
            mma_bf16(tmp[pb], al[0][mi][0], al[0][mi][1], al[0][mi][2], al[0][mi][3],
                     bh[0][ni][0], bh[0][ni][1]);
            mma_bf16(tmp[pb], ah[1][mi][0], ah[1][mi][1], ah[1][mi][2], ah[1][mi][3],
                     bh[1][ni][0], bh[1][ni][1]);
            mma_bf16(tmp[pb], al[1][mi][0], al[1][mi][1], al[1][mi][2], al[1][mi][3],
                     bh[1][ni][0], bh[1][ni][1]);
            if (u > 0) {
                int v = u - 1, vm = v >> 2, vn = v & 3, vb = v & 1;
                acc[vm][vn][0] += tmp[vb][0] * sreg[vn][0];
                acc[vm][vn][1] += tmp[vb][1] * sreg[vn][1];
                acc[vm][vn][2] += tmp[vb][2] * sreg[vn][0];
                acc[vm][vn][3] += tmp[vb][3] * sreg[vn][1];
            }
        }
        acc[3][3][0] += tmp[1][0] * sreg[3][0];
        acc[3][3][1] += tmp[1][1] * sreg[3][1];
        acc[3][3][2] += tmp[1][2] * sreg[3][0];
        acc[3][3][3] += tmp[1][3] * sreg[3][1];

        if (hasNext) CP_WAIT0();
        __syncthreads();
    }

    // ---- epilogue (store or atomic-accumulate) ----
#pragma unroll
    for (int ni = 0; ni < 4; ni++) {
        int n = scol[ni];
        float b0 = 0.f, b1 = 0.f;
        if (bias) { b0 = bias[n]; b1 = bias[n + 1]; }
#pragma unroll
        for (int mi = 0; mi < 4; mi++) {
            int m = bm + warp_m * 64 + mi * 16 + g;
            float* p0 = C + (size_t)m * N + n;
            float* p1 = C + (size_t)(m + 8) * N + n;
            if (atomic) {
                atomicAdd(p0,     acc[mi][ni][0]);
                atomicAdd(p0 + 1, acc[mi][ni][1]);
                atomicAdd(p1,     acc[mi][ni][2]);
                atomicAdd(p1 + 1, acc[mi][ni][3]);
            } else {
                *(float2*)p0 = make_float2(acc[mi][ni][0] + b0, acc[mi][ni][1] + b1);
                *(float2*)p1 = make_float2(acc[mi][ni][2] + b0, acc[mi][ni][3] + b1);
            }
        }
    }
}

__global__ __launch_bounds__(256, 2)
void gemm_qkv_kernel(const __nv_bfloat16* __restrict__ xh,
                     const __nv_bfloat16* __restrict__ xl,
    const int* __restrict__ qwq, const float* __restrict__ scq,
    const int* __restrict__ qzq, const float* __restrict__ bq,
    const int* __restrict__ qwk, const float* __restrict__ sck,
    const int* __restrict__ qzk, const float* __restrict__ bk,
    const int* __restrict__ qwv, const float* __restrict__ scv,
    const int* __restrict__ qzv, const float* __restrict__ bv,
    float* __restrict__ Cq, float* __restrict__ Ck, float* __restrict__ Cv)
{
    extern __shared__ unsigned gsm[];
    int bt = blockIdx.x;
    int bm = blockIdx.y * BM;
    const int* qw; const float* sc; const int* qz; const float* bias;
    float* C; int N; int bn;
    if (bt < 32)      { qw = qwq; sc = scq; qz = qzq; bias = bq; C = Cq; N = QDIM;  bn = bt * BN; }
    else if (bt < 40) { qw = qwk; sc = sck; qz = qzk; bias = bk; C = Ck; N = KVDIM; bn = (bt - 32) * BN; }
    else              { qw = qwv; sc = scv; qz = qzv; bias = bv; C = Cv; N = KVDIM; bn = (bt - 40) * BN; }
    gemm_core(xh, xl, qw, sc, qz, bias, C, N, HIDDEN, HIDDEN, bm, bn, false, gsm);
}

// O projection: split-K over blockIdx.z (OSPLIT slices of 1024), atomicAdd.
__global__ __launch_bounds__(256, 2)
void gemm_o_kernel(const __nv_bfloat16* __restrict__ ah,
                   const __nv_bfloat16* __restrict__ al,
                   const int* __restrict__ qw, const float* __restrict__ sc,
                   const int* __restrict__ qz, float* __restrict__ C)
{
    extern __shared__ unsigned gsm[];
    const int klen = QDIM / OSPLIT;            // 1024
    int kb = blockIdx.z * klen;
    gemm_core(ah + kb, al + kb,
              qw + (size_t)(kb >> 3) * HIDDEN,
              sc + (size_t)(kb >> 7) * HIDDEN,
              qz + (size_t)(kb >> 7) * HIDDEN,
              nullptr, C, HIDDEN, QDIM, klen,
              blockIdx.y * BM, blockIdx.x * BN, true, gsm);
}

// ======================================================================
// RoPE + split (unchanged)
// ======================================================================
__global__ __launch_bounds__(256)
void rope_split_kernel(float* __restrict__ Qb,
                       const float* __restrict__ Kf,
                       const float* __restrict__ Vf,
                       __nv_bfloat16* __restrict__ Kh, __nv_bfloat16* __restrict__ Kl,
                       __nv_bfloat16* __restrict__ Vh, __nv_bfloat16* __restrict__ Vl,
                       const float* __restrict__ cosb,
                       const float* __restrict__ sinb)
{
    int s = blockIdx.y;
    int h = blockIdx.x * 4 + (threadIdx.x >> 6);
    int d = threadIdx.x & 63;

    if (h < NH) {
        float c1 = cosb[s * HD + d],     s1 = sinb[s * HD + d];
        float c2 = cosb[s * HD + d + 64], s2 = sinb[s * HD + d + 64];
        float* base = Qb + (size_t)s * QDIM + h * HD;
        float x1 = base[d], x2 = base[d + 64];
        base[d]      = x1 * c1 - x2 * s1;
        base[d + 64] = x2 * c2 + x1 * s2;
    } else if (h < NH + NKV) {
        int kh = h - NH;
        float c1 = cosb[s * HD + d],     s1 = sinb[s * HD + d];
        float c2 = cosb[s * HD + d + 64], s2 = sinb[s * HD + d + 64];
        const float* base = Kf + (size_t)s * KVDIM + kh * HD;
        float x1 = base[d], x2 = base[d + 64];
        float y1 = x1 * c1 - x2 * s1;
        float y2 = x2 * c2 + x1 * s2;
        size_t o = (size_t)s * KVDIM + kh * HD + d;
        __nv_bfloat16 h1 = __float2bfloat16(y1);
        __nv_bfloat16 h2 = __float2bfloat16(y2);
        Kh[o] = h1;       Kl[o] = __float2bfloat16(y1 - __bfloat162float(h1));
        Kh[o + 64] = h2;  Kl[o + 64] = __float2bfloat16(y2 - __bfloat162float(h2));
    } else {
        int vh = h - NH - NKV;
        const float* base = Vf + (size_t)s * KVDIM + vh * HD;
        float x1 = base[d], x2 = base[d + 64];
        size_t o = (size_t)s * KVDIM + vh * HD + d;
        __nv_bfloat16 h1 = __float2bfloat16(x1);
        __nv_bfloat16 h2 = __float2bfloat16(x2);
        Vh[o] = h1;       Vl[o] = __float2bfloat16(x1 - __bfloat162float(h1));
        Vh[o + 64] = h2;  Vl[o + 64] = __float2bfloat16(x2 - __bfloat162float(h2));
    }
}

// ======================================================================
// bf16x3 flash attention (unchanged from R13; validated)
// ======================================================================
#define FBQ 64
#define FBK 64
#define FTHREADS 128
#define KVW 68
#define FPLANE (FBK * KVW)

__global__ __launch_bounds__(FTHREADS, 2)
void flash_tc_kernel(const float* __restrict__ Q,
                     const __nv_bfloat16* __restrict__ Kh,
                     const __nv_bfloat16* __restrict__ Kl,
                     const __nv_bfloat16* __restrict__ Vh,
                     const __nv_bfloat16* __restrict__ Vl,
                     __nv_bfloat16* __restrict__ Oh,
                     __nv_bfloat16* __restrict__ Ol)
{
    extern __shared__ unsigned fsm[];
    unsigned (*KsH)[KVW] = (unsigned(*)[KVW])(fsm);
    unsigned (*KsL)[KVW] = (unsigned(*)[KVW])(fsm + FPLANE);
    unsigned (*VsH)[KVW] = (unsigned(*)[KVW])(fsm + 2 * FPLANE);
    unsigned (*VsL)[KVW] = (unsigned(*)[KVW])(fsm + 3 * FPLANE);

    int h = blockIdx.y;
    int qt = gridDim.x - 1 - blockIdx.x;
    int q0 = qt * FBQ;
    int kvh = h >> 2;
    int tid = threadIdx.x, lane = tid & 31, warp = tid >> 5;
    int t = lane & 3, g = lane >> 2;

    unsigned kbH = smem_u32(KsH), kbL = smem_u32(KsL);
    unsigned vbH = smem_u32(VsH), vbL = smem_u32(VsL);

    const __nv_bfloat16* Khb = Kh + kvh * HD;
    const __nv_bfloat16* Klb = Kl + kvh * HD;
    const __nv_bfloat16* Vhb = Vh + kvh * HD;
    const __nv_bfloat16* Vlb = Vl + kvh * HD;

    unsigned qh[8][4], ql[8][4];
    {
        const float sc = 0.08838834764831845f;
        int r0 = q0 + warp * 16 + g;
        const float* p0 = Q + (size_t)r0 * QDIM + h * HD;
        const float* p1 = p0 + 8 * QDIM;
#pragma unroll
        for (int ks = 0; ks < 8; ks++) {
            int d = ks * 16 + 2 * t;
            float2 a0 = *(const float2*)(p0 + d);
            float2 a1 = *(const float2*)(p1 + d);
            float2 a2 = *(const float2*)(p0 + d + 8);
            float2 a3 = *(const float2*)(p1 + d + 8);
            split2(a0.x * sc, a0.y * sc, qh[ks][0], ql[ks][0]);
            split2(a1.x * sc, a1.y * sc, qh[ks][1], ql[ks][1]);
            split2(a2.x * sc, a2.y * sc, qh[ks][2], ql[ks][2]);
            split2(a3.x * sc, a3.y * sc, qh[ks][3], ql[ks][3]);
        }
    }

    float m0 = -INFINITY, m1 = -INFINITY, l0s = 0.f, l1s = 0.f;
    float o_acc[16][4];
#pragma unroll
    for (int nj = 0; nj < 16; nj++)
#pragma unroll
        for (int r = 0; r < 4; r++) o_acc[nj][r] = 0.f;

    int ntiles = qt + 1;

#pragma unroll
    for (int i = 0; i < 8; i++) {
        int idx = tid + i * FTHREADS;
        int r = idx >> 4;
        int ch = idx & 15;
        size_t off = (size_t)r * KVDIM + ch * 8;
        unsigned d = (unsigned)(r * KVW + ch * 4) * 4;
        cp_async16(kbH + d, Khb + off);
        cp_async16(kbL + d, Klb + off);
    }
    CP_COMMIT();
#pragma unroll
    for (int i = 0; i < 8; i++) {
        int idx = tid + i * FTHREADS;
        int r = idx >> 4;
        int ch = idx & 15;
        size_t off = (size_t)r * KVDIM + ch * 8;
        unsigned d = (unsigned)(r * KVW + ch * 4) * 4;
        cp_async16(vbH + d, Vhb + off);
        cp_async16(vbL + d, Vlb + off);
    }
    CP_COMMIT();

    for (int tt = 0; tt < ntiles; tt++) {
        bool hasNext = (tt + 1 < ntiles);

        CP_WAIT1();
        __syncthreads();

        float s[8][4];
#pragma unroll
        for (int ni = 0; ni < 8; ni++)
#pragma unroll
            for (int r = 0; r < 4; r++) s[ni][r] = 0.f;

#pragma unroll
        for (int ks = 0; ks < 8; ks++) {
            int w = ks * 8 + t;
#pragma unroll
            for (int ni = 0; ni < 8; ni++) {
                int col = ni * 8 + g;
                unsigned bh0 = KsH[col][w], bh1 = KsH[col][w + 4];
                unsigned bl0 = KsL[col][w], bl1 = KsL[col][w + 4];
                mma_bf16(s[ni], qh[ks][0], qh[ks][1], qh[ks][2], qh[ks][3], bh0, bh1);
                mma_bf16(s[ni], qh[ks][0], qh[ks][1], qh[ks][2], qh[ks][3], bl0, bl1);
                mma_bf16(s[ni], ql[ks][0], ql[ks][1], ql[ks][2], ql[ks][3], bh0, bh1);
            }
        }
        __syncthreads();

        if (hasNext) {
            int kb1 = (tt + 1) << 6;
#pragma unroll
            for (int i = 0; i < 8; i++) {
                int idx = tid + i * FTHREADS;
                int r = idx >> 4;
                int ch = idx & 15;
                size_t off = (size_t)(kb1 + r) * KVDIM + ch * 8;
                unsigned d = (unsigned)(r * KVW + ch * 4) * 4;
                cp_async16(kbH + d, Khb + off);
                cp_async16(kbL + d, Klb + off);
            }
            CP_COMMIT();
            CP_WAIT1();
        } else {
            CP_WAIT0();
        }

        int kb = tt << 6;
        if (kb + FBK > q0) {
            int r0 = q0 + warp * 16 + g, r1 = r0 + 8;
#pragma unroll
            for (int ni = 0; ni < 8; ni++) {
                int c0 = kb + ni * 8 + 2 * t, c1 = c0 + 1;
                if (c0 > r0) s[ni][0] = -INFINITY;
                if (c1 > r0) s[ni][1] = -INFINITY;
                if (c0 > r1) s[ni][2] = -INFINITY;
                if (c1 > r1) s[ni][3] = -INFINITY;
            }
        }

        float rm0 = -INFINITY, rm1 = -INFINITY;
#pragma unroll
        for (int ni = 0; ni < 8; ni++) {
            rm0 = fmaxf(rm0, fmaxf(s[ni][0], s[ni][1]));
            rm1 = fmaxf(rm1, fmaxf(s[ni][2], s[ni][3]));
        }
        rm0 = fmaxf(rm0, __shfl_xor_sync(0xffffffffu, rm0, 1));
        rm0 = fmaxf(rm0, __shfl_xor_sync(0xffffffffu, rm0, 2));
        rm1 = fmaxf(rm1, __shfl_xor_sync(0xffffffffu, rm1, 1));
        rm1 = fmaxf(rm1, __shfl_xor_sync(0xffffffffu, rm1, 2));
        float mn0 = fmaxf(m0, rm0), mn1 = fmaxf(m1, rm1);
        float cr0 = __expf(m0 - mn0), cr1 = __expf(m1 - mn1);
        m0 = mn0; m1 = mn1;
        float ps0 = 0.f, ps1 = 0.f;
#pragma unroll
        for (int ni = 0; ni < 8; ni++) {
            s[ni][0] = __expf(s[ni][0] - mn0);
            s[ni][1] = __expf(s[ni][1] - mn0);
            s[ni][2] = __expf(s[ni][2] - mn1);
            s[ni][3] = __expf(s[ni][3] - mn1);
            ps0 += s[ni][0] + s[ni][1];
            ps1 += s[ni][2] + s[ni][3];
        }
        ps0 += __shfl_xor_sync(0xffffffffu, ps0, 1);
        ps0 += __shfl_xor_sync(0xffffffffu, ps0, 2);
        ps1 += __shfl_xor_sync(0xffffffffu, ps1, 1);
        ps1 += __shfl_xor_sync(0xffffffffu, ps1, 2);
        l0s = l0s * cr0 + ps0;
        l1s = l1s * cr1 + ps1;
#pragma unroll
        for (int nj = 0; nj < 16; nj++) {
            o_acc[nj][0] *= cr0; o_acc[nj][1] *= cr0;
            o_acc[nj][2] *= cr1; o_acc[nj][3] *= cr1;
        }

        __syncthreads();

#pragma unroll
        for (int ks2 = 0; ks2 < 4; ks2++) {
            unsigned ph[4], pl[4];
            split2(s[2 * ks2][0],     s[2 * ks2][1],     ph[0], pl[0]);
            split2(s[2 * ks2][2],     s[2 * ks2][3],     ph[1], pl[1]);
            split2(s[2 * ks2 + 1][0], s[2 * ks2 + 1][1], ph[2], pl[2]);
            split2(s[2 * ks2 + 1][2], s[2 * ks2 + 1][3], ph[3], pl[3]);
            unsigned rowb = (unsigned)(ks2 * 16 + (lane & 15)) * (KVW * 4);
#pragma unroll
            for (int nj = 0; nj < 16; nj++) {
                unsigned v0, v1, u0, u1;
                ldsm_x2_trans(v0, v1, vbH + rowb + nj * 16);
                ldsm_x2_trans(u0, u1, vbL + rowb + nj * 16);
                mma_bf16(o_acc[nj], ph[0], ph[1], ph[2], ph[3], v0, v1);
                mma_bf16(o_acc[nj], ph[0], ph[1], ph[2], ph[3], u0, u1);
                mma_bf16(o_acc[nj], pl[0], pl[1], pl[2], pl[3], v0, v1);
            }
        }
        __syncthreads();

        if (hasNext) {
            int kb1 = (tt + 1) << 6;
#pragma unroll
            for (int i = 0; i < 8; i++) {
                int idx = tid + i * FTHREADS;
                int r = idx >> 4;
                int ch = idx & 15;
                size_t off = (size_t)(kb1 + r) * KVDIM + ch * 8;
                unsigned d = (unsigned)(r * KVW + ch * 4) * 4;
                cp_async16(vbH + d, Vhb + off);
                cp_async16(vbL + d, Vlb + off);
            }
            CP_COMMIT();
        }
    }

    float inv0 = 1.f / l0s, inv1 = 1.f / l1s;
    int r0 = q0 + warp * 16 + g;
    size_t b0 = (size_t)r0 * QDIM + h * HD;
    size_t b1 = b0 + 8 * (size_t)QDIM;
#pragma unroll
    for (int nj = 0; nj < 16; nj++) {
        int d = nj * 8 + 2 * t;
        unsigned hh, ll;
        split2(o_acc[nj][0] * inv0, o_acc[nj][1] * inv0, hh, ll);
        *(unsigned*)(Oh + b0 + d) = hh;
        *(unsigned*)(Ol + b0 + d) = ll;
        split2(o_acc[nj][2] * inv1, o_acc[nj][3] * inv1, hh, ll);
        *(unsigned*)(Oh + b1 + d) = hh;
        *(unsigned*)(Ol + b1 + d) = ll;
    }
}

// ======================================================================
// Launch
// ======================================================================
extern "C" void kernel_launch(void* const* d_in, const int* in_sizes, int n_in,
                              void* d_out, int out_size)
{
    const float* x        = (const float*)d_in[0];
    const float* cosb     = (const float*)d_in[1];
    const float* sinb     = (const float*)d_in[2];
    const float* q_scales = (const float*)d_in[3];
    const float* q_bias   = (const float*)d_in[4];
    const float* k_scales = (const float*)d_in[5];
    const float* k_bias   = (const float*)d_in[6];
    const float* v_scales = (const float*)d_in[7];
    const float* v_bias   = (const float*)d_in[8];
    const float* o_scales = (const float*)d_in[9];
    const int* q_qweight  = (const int*)d_in[10];
    const int* q_qzeros   = (const int*)d_in[11];
    const int* k_qweight  = (const int*)d_in[12];
    const int* k_qzeros   = (const int*)d_in[13];
    const int* v_qweight  = (const int*)d_in[14];
    const int* v_qzeros   = (const int*)d_in[15];
    const int* o_qweight  = (const int*)d_in[16];
    const int* o_qzeros   = (const int*)d_in[17];
    float* out = (float*)d_out;

    float *pq, *pk, *pv;
    __nv_bfloat16 *pxh, *pxl, *pkh, *pkl, *pvh, *pvl, *pah, *pal;
    cudaGetSymbolAddress((void**)&pq, g_q);
    cudaGetSymbolAddress((void**)&pk, g_k);
    cudaGetSymbolAddress((void**)&pv, g_v);
    cudaGetSymbolAddress((void**)&pxh, g_xh);
    cudaGetSymbolAddress((void**)&pxl, g_xl);
    cudaGetSymbolAddress((void**)&pkh, g_kh);
    cudaGetSymbolAddress((void**)&pkl, g_kl);
    cudaGetSymbolAddress((void**)&pvh, g_vh);
    cudaGetSymbolAddress((void**)&pvl, g_vl);
    cudaGetSymbolAddress((void**)&pah, g_ah);
    cudaGetSymbolAddress((void**)&pal, g_al);

    size_t gsmem = (size_t)(2 * GBUF) * sizeof(unsigned);
    cudaFuncSetAttribute(gemm_qkv_kernel,
                         cudaFuncAttributeMaxDynamicSharedMemorySize, (int)gsmem);
    cudaFuncSetAttribute(gemm_o_kernel,
                         cudaFuncAttributeMaxDynamicSharedMemorySize, (int)gsmem);

    // presplit x
    presplit_kernel<<<(S_LEN * HIDDEN / 2) / 256, 256>>>(x, pxh, pxl);

    // fused QKV projection
    {
        dim3 grid(48, S_LEN / BM);
        gemm_qkv_kernel<<<grid, 256, gsmem>>>(
            pxh, pxl,
            q_qweight, q_scales, q_qzeros, q_bias,
            k_qweight, k_scales, k_qzeros, k_bias,
            v_qweight, v_scales, v_qzeros, v_bias,
            pq, pk, pv);
    }

    // RoPE (Q in-place) + K/V presplit
    {
        dim3 grid(12, S_LEN);
        rope_split_kernel<<<grid, 256>>>(pq, pk, pv, pkh, pkl, pvh, pvl, cosb, sinb);
    }

    // Flash attention
    {
        size_t smem = (size_t)(4 * FPLANE) * sizeof(unsigned);
        cudaFuncSetAttribute(flash_tc_kernel,
                             cudaFuncAttributeMaxDynamicSharedMemorySize, (int)smem);
        dim3 grid(S_LEN / FBQ, NH);
        flash_tc_kernel<<<grid, FTHREADS, smem>>>(pq, pkh, pkl, pvh, pvl, pah, pal);
    }

    // O projection: zero-init + split-K=4 with atomicAdd accumulation
    {
        zero_kernel<<<(S_LEN * HIDDEN / 4) / 256, 256>>>(out);
        dim3 go(HIDDEN / BN, S_LEN / BM, OSPLIT);
        gemm_o_kernel<<<go, 256, gsmem>>>(pah, pal, o_qweight, o_scales, o_qzeros, out);
    }
}

// round 16
// speedup vs baseline: 1.0964x; 1.0060x over previous
#include <cuda_runtime.h>
#include <cuda_bf16.h>
#include <math.h>

// Problem constants
#define S_LEN 2048
#define HIDDEN 2560
#define NH 32
#define NKV 8
#define HD 128
#define QDIM (NH*HD)    // 4096
#define KVDIM (NKV*HD)  // 1024
#define GS 128
#define OSPLIT 4        // split-K factor for O projection

#define QKV_TILES 768   // 48 x 16
#define O_TILES   (20 * 16 * OSPLIT)   // 1280
#define PGRID     296   // 2 CTAs/SM x 148 SMs

// -------- scratch (static device arrays; no allocation allowed) --------
__device__ float g_q[S_LEN * QDIM];
__device__ float g_k[S_LEN * KVDIM];
__device__ float g_v[S_LEN * KVDIM];
__device__ __nv_bfloat16 g_xh[S_LEN * HIDDEN], g_xl[S_LEN * HIDDEN];
__device__ __nv_bfloat16 g_kh[S_LEN * KVDIM], g_kl[S_LEN * KVDIM];
__device__ __nv_bfloat16 g_vh[S_LEN * KVDIM], g_vl[S_LEN * KVDIM];
__device__ __nv_bfloat16 g_ah[S_LEN * QDIM],  g_al[S_LEN * QDIM];
__device__ unsigned g_ctr_qkv, g_ctr_o;

// ======================================================================
// helpers
// ======================================================================
__device__ __forceinline__ void split2(float f0, float f1,
                                       unsigned &hi, unsigned &lo) {
    __nv_bfloat16 h0 = __float2bfloat16(f0);
    __nv_bfloat16 h1 = __float2bfloat16(f1);
    __nv_bfloat16 l0 = __float2bfloat16(f0 - __bfloat162float(h0));
    __nv_bfloat16 l1 = __float2bfloat16(f1 - __bfloat162float(h1));
    hi = (unsigned)__bfloat16_as_ushort(h0) |
         ((unsigned)__bfloat16_as_ushort(h1) << 16);
    lo = (unsigned)__bfloat16_as_ushort(l0) |
         ((unsigned)__bfloat16_as_ushort(l1) << 16);
}

__device__ __forceinline__ unsigned pack2(float f0, float f1) {
    return (unsigned)__bfloat16_as_ushort(__float2bfloat16(f0)) |
           ((unsigned)__bfloat16_as_ushort(__float2bfloat16(f1)) << 16);
}

__device__ __forceinline__ void mma_bf16(float c[4],
                                         unsigned a0, unsigned a1, unsigned a2, unsigned a3,
                                         unsigned b0, unsigned b1) {
    asm volatile(
        "mma.sync.aligned.m16n8k16.row.col.f32.bf16.bf16.f32 "
        "{%0,%1,%2,%3}, {%4,%5,%6,%7}, {%8,%9}, {%0,%1,%2,%3};"
        : "+f"(c[0]), "+f"(c[1]), "+f"(c[2]), "+f"(c[3])
        : "r"(a0), "r"(a1), "r"(a2), "r"(a3), "r"(b0), "r"(b1));
}

__device__ __forceinline__ void ldsm_x2_trans(unsigned &r0, unsigned &r1, unsigned addr) {
    asm volatile("ldmatrix.sync.aligned.m8n8.x2.trans.shared.b16 {%0,%1}, [%2];"
                 : "=r"(r0), "=r"(r1) : "r"(addr));
}

__device__ __forceinline__ unsigned smem_u32(const void* p) {
    return (unsigned)__cvta_generic_to_shared(p);
}

__device__ __forceinline__ void cp_async16(unsigned dst, const void* src) {
    asm volatile("cp.async.cg.shared.global [%0], [%1], 16;" :: "r"(dst), "l"(src));
}
#define CP_COMMIT() asm volatile("cp.async.commit_group;" ::: "memory")
#define CP_WAIT0()  asm volatile("cp.async.wait_group 0;" ::: "memory")
#define CP_WAIT1()  asm volatile("cp.async.wait_group 1;" ::: "memory")

// ======================================================================
// presplit / zero / counter-reset
// ======================================================================
__global__ __launch_bounds__(256)
void presplit_kernel(const float* __restrict__ x,
                     __nv_bfloat16* __restrict__ xh,
                     __nv_bfloat16* __restrict__ xl)
{
    int i = blockIdx.x * 256 + threadIdx.x;
    float2 v = ((const float2*)x)[i];
    unsigned h, l;
    split2(v.x, v.y, h, l);
    ((unsigned*)xh)[i] = h;
    ((unsigned*)xl)[i] = l;
}

__global__ __launch_bounds__(256)
void zero_kernel(float* __restrict__ p)
{
    int i = blockIdx.x * 256 + threadIdx.x;
    ((float4*)p)[i] = make_float4(0.f, 0.f, 0.f, 0.f);
}

__global__ void reset_ctr_kernel()
{
    g_ctr_qkv = 0;
    g_ctr_o = 0;
}

// ======================================================================
// Dequant GEMM core (validated): presplit A + exact-int4 B + scale fold
// ======================================================================
#define BM 128
#define BN 128
#define BK 32
#define GST 20
#define GPL (128 * GST)
#define GBUF (3 * GPL)

__device__ __forceinline__ void gemm_core(
    const __nv_bfloat16* __restrict__ Ahp,
    const __nv_bfloat16* __restrict__ Alp,
    const int*   __restrict__ qw,
    const float* __restrict__ sc,
    const int*   __restrict__ qz,
    const float* __restrict__ bias,
    float* __restrict__ C,
    int N, int Kstride, int Klen, int bm, int bn, bool atomic, unsigned* gsm)
{
    unsigned sbase = smem_u32(gsm);

    int tid  = threadIdx.x;
    int lane = tid & 31;
    int warp = tid >> 5;
    int warp_m = warp & 1;
    int warp_n = warp >> 1;
    int t = lane & 3;
    int g = lane >> 2;

    int am[2], ach[2];
#pragma unroll
    for (int i = 0; i < 2; i++) {
        int c = tid + i * 256;
        am[i]  = c >> 2;
        ach[i] = c & 3;
    }
    int n_loc = tid & 127;
    int kp0   = (tid >> 7) << 1;

    int scol[4];
#pragma unroll
    for (int ni = 0; ni < 4; ni++)
        scol[ni] = bn + warp_n * 32 + ni * 8 + (t << 1);

    float acc[4][4][4];
#pragma unroll
    for (int mi = 0; mi < 4; mi++)
#pragma unroll
        for (int ni = 0; ni < 4; ni++)
#pragma unroll
            for (int r = 0; r < 4; r++) acc[mi][ni][r] = 0.f;

    float sreg[4][2];
    unsigned bw[2];
    float bz;

    int T = Klen / BK;

    {
        unsigned b0 = sbase;
#pragma unroll
        for (int i = 0; i < 2; i++) {
            const __nv_bfloat16* sh = Ahp + (size_t)(bm + am[i]) * Kstride + ach[i] * 8;
            const __nv_bfloat16* sl = Alp + (size_t)(bm + am[i]) * Kstride + ach[i] * 8;
            unsigned d = (unsigned)(am[i] * GST + ach[i] * 4) * 4;
            cp_async16(b0 + d, sh);
            cp_async16(b0 + GPL * 4 + d, sl);
        }
        CP_COMMIT();
        const int* qp = qw + (size_t)kp0 * N + bn + n_loc;
        bw[0] = (unsigned)qp[0];
        bw[1] = (unsigned)qp[N];
        bz = (float)qz[bn + n_loc];
        unsigned* Bs = gsm + 2 * GPL;
#pragma unroll
        for (int i = 0; i < 2; i++) {
            unsigned q = bw[i];
            int kpb = (kp0 + i) * 4;
#pragma unroll
            for (int j = 0; j < 4; j++)
                Bs[n_loc * GST + kpb + j] =
                    pack2((float)((q >> (8 * j)) & 15u) - bz,
                          (float)((q >> (8 * j + 4)) & 15u) - bz);
        }
        if (T > 1) {
            const int* qp1 = qw + (size_t)(4 + kp0) * N + bn + n_loc;
            bw[0] = (unsigned)qp1[0];
            bw[1] = (unsigned)qp1[N];
            bz = (float)qz[(size_t)(BK >> 7) * N + bn + n_loc];
        }
        CP_WAIT0();
        __syncthreads();
    }

    for (int it = 0; it < T; it++) {
        int k0 = it * BK;
        int b = it & 1;
        unsigned* base = gsm + b * GBUF;
        bool hasNext = (it + 1 < T);

        if (hasNext) {
            int kn = k0 + BK;
            unsigned nb = sbase + ((b ^ 1) * GBUF) * 4;
#pragma unroll
            for (int i = 0; i < 2; i++) {
                const __nv_bfloat16* sh = Ahp + (size_t)(bm + am[i]) * Kstride + kn + ach[i] * 8;
                const __nv_bfloat16* sl = Alp + (size_t)(bm + am[i]) * Kstride + kn + ach[i] * 8;
                unsigned d = (unsigned)(am[i] * GST + ach[i] * 4) * 4;
                cp_async16(nb + d, sh);
                cp_async16(nb + GPL * 4 + d, sl);
            }
            CP_COMMIT();
            unsigned* nBs = gsm + (b ^ 1) * GBUF + 2 * GPL;
#pragma unroll
            for (int i = 0; i < 2; i++) {
                unsigned q = bw[i];
                int kpb = (kp0 + i) * 4;
#pragma unroll
                for (int j = 0; j < 4; j++)
                    nBs[n_loc * GST + kpb + j] =
                        pack2((float)((q >> (8 * j)) & 15u) - bz,
                              (float)((q >> (8 * j + 4)) & 15u) - bz);
            }
            if (it + 2 < T) {
                int kn2 = k0 + 2 * BK;
                const int* qp = qw + (size_t)((kn2 >> 3) + kp0) * N + bn + n_loc;
                bw[0] = (unsigned)qp[0];
                bw[1] = (unsigned)qp[N];
                bz = (float)qz[(size_t)(kn2 >> 7) * N + bn + n_loc];
            }
        }

        if ((k0 & 127) == 0) {
            int grp = k0 >> 7;
#pragma unroll
            for (int ni = 0; ni < 4; ni++) {
                sreg[ni][0] = sc[(size_t)grp * N + scol[ni]];
                sreg[ni][1] = sc[(size_t)grp * N + scol[ni] + 1];
            }
        }

        const unsigned* AsH = base;
        const unsigned* AsL = base + GPL;
        const unsigned* Bs  = base + 2 * GPL;
        unsigned ah[2][4][4], al[2][4][4], bh[2][4][2];
#pragma unroll
        for (int ks = 0; ks < 2; ks++) {
            int kpb = ks * 8;
#pragma unroll
            for (int mi = 0; mi < 4; mi++) {
                int r = warp_m * 64 + mi * 16 + g;
                ah[ks][mi][0] = AsH[r * GST + kpb + t];
                ah[ks][mi][1] = AsH[(r + 8) * GST + kpb + t];
                ah[ks][mi][2] = AsH[r * GST + kpb + t + 4];
                ah[ks][mi][3] = AsH[(r + 8) * GST + kpb + t + 4];
                al[ks][mi][0] = AsL[r * GST + kpb + t];
                al[ks][mi][1] = AsL[(r + 8) * GST + kpb + t];
                al[ks][mi][2] = AsL[r * GST + kpb + t + 4];
                al[ks][mi][3] = AsL[(r + 8) * GST + kpb + t + 4];
            }
#pragma unroll
            for (int ni = 0; ni < 4; ni++) {
                int c = warp_n * 32 + ni * 8 + g;
                bh[ks][ni][0] = Bs[c * GST + kpb + t];
                bh[ks][ni][1] = Bs[c * GST + kpb + t + 4];
            }
        }

        float tmp[2][4];
#pragma unroll
        for (int u = 0; u < 16; u++) {
            int mi = u >> 2, ni = u & 3, pb = u & 1;
            tmp[pb][0] = 0.f; tmp[pb][1] = 0.f;
            tmp[pb][2] = 0.f; tmp[pb][3] = 0.f;
            mma_bf16(tmp[pb], ah[0][mi][0], ah[0][mi][1], ah[0][mi][2], ah[0][mi][3],
                     bh[0][ni][0], bh[0][ni][1]);
            mma_bf16(tmp[pb], al[0][mi][0], al[0][mi][1], al[0][mi][2], al[0][mi][3],
                     bh[0][ni][0], bh[0][ni][1]);
            mma_bf16(tmp[pb], ah[1][mi][0], ah[1][mi][1], ah[1][mi][2], ah[1][mi][3],
                     bh[1][ni][0], bh[1][ni][1]);
            mma_bf16(tmp[pb], al[1][mi][0], al[1][mi][1], al[1][mi][2], al[1][mi][3],
                     bh[1][ni][0], bh[1][ni][1]);
            if (u > 0) {
                int v = u - 1, vm = v >> 2, vn = v & 3, vb = v & 1;
                acc[vm][vn][0] += tmp[vb][0] * sreg[vn][0];
                acc[vm][vn][1] += tmp[vb][1] * sreg[vn][1];
                acc[vm][vn][2] += tmp[vb][2] * sreg[vn][0];
                acc[vm][vn][3] += tmp[vb][3] * sreg[vn][1];
            }
        }
        acc[3][3][0] += tmp[1][0] * sreg[3][0];
        acc[3][3][1] += tmp[1][1] * sreg[3][1];
        acc[3][3][2] += tmp[1][2] * sreg[3][0];
        acc[3][3][3] += tmp[1][3] * sreg[3][1];

        if (hasNext) CP_WAIT0();
        __syncthreads();
    }

    // ---- epilogue (store or atomic-accumulate) ----
#pragma unroll
    for (int ni = 0; ni < 4; ni++) {
        int n = scol[ni];
        float b0 = 0.f, b1 = 0.f;
        if (bias) { b0 = bias[n]; b1 = bias[n + 1]; }
#pragma unroll
        for (int mi = 0; mi < 4; mi++) {
            int m = bm + warp_m * 64 + mi * 16 + g;
            float* p0 = C + (size_t)m * N + n;
            float* p1 = C + (size_t)(m + 8) * N + n;
            if (atomic) {
                atomicAdd(p0,     acc[mi][ni][0]);
                atomicAdd(p0 + 1, acc[mi][ni][1]);
                atomicAdd(p1,     acc[mi][ni][2]);
                atomicAdd(p1 + 1, acc[mi][ni][3]);
            } else {
                *(float2*)p0 = make_float2(acc[mi][ni][0] + b0, acc[mi][ni][1] + b1);
                *(float2*)p1 = make_float2(acc[mi][ni][2] + b0, acc[mi][ni][3] + b1);
            }
        }
    }
}

// ---- persistent QKV: 296 CTAs steal tiles from g_ctr_qkv ----
__global__ __launch_bounds__(256, 2)
void gemm_qkv_kernel(const __nv_bfloat16* __restrict__ xh,
                     const __nv_bfloat16* __restrict__ xl,
    const int* __restrict__ qwq, const float* __restrict__ scq,
    const int* __restrict__ qzq, const float* __restrict__ bq,
    const int* __restrict__ qwk, const float* __restrict__ sck,
    const int* __restrict__ qzk, const float* __restrict__ bk,
    const int* __restrict__ qwv, const float* __restrict__ scv,
    const int* __restrict__ qzv, const float* __restrict__ bv,
    float* __restrict__ Cq, float* __restrict__ Ck, float* __restrict__ Cv)
{
    extern __shared__ unsigned gsm[];
    __shared__ unsigned tile_s;

    for (;;) {
        if (threadIdx.x == 0) tile_s = atomicAdd(&g_ctr_qkv, 1u);
        __syncthreads();
        unsigned tile = tile_s;
        if (tile >= QKV_TILES) return;

        int bt = (int)(tile % 48u);
        int bm = (int)(tile / 48u) * BM;
        const int* qw; const float* sc; const int* qz; const float* bias;
        float* C; int N; int bn;
        if (bt < 32)      { qw = qwq; sc = scq; qz = qzq; bias = bq; C = Cq; N = QDIM;  bn = bt * BN; }
        else if (bt < 40) { qw = qwk; sc = sck; qz = qzk; bias = bk; C = Ck; N = KVDIM; bn = (bt - 32) * BN; }
        else              { qw = qwv; sc = scv; qz = qzv; bias = bv; C = Cv; N = KVDIM; bn = (bt - 40) * BN; }
        gemm_core(xh, xl, qw, sc, qz, bias, C, N, HIDDEN, HIDDEN, bm, bn, false, gsm);
    }
}

// ---- persistent O projection: split-K=4, z-major tile order, atomicAdd ----
__global__ __launch_bounds__(256, 2)
void gemm_o_kernel(const __nv_bfloat16* __restrict__ ah,
                   const __nv_bfloat16* __restrict__ al,
                   const int* __restrict__ qw, const float* __restrict__ sc,
                   const int* __restrict__ qz, float* __restrict__ C)
{
    extern __shared__ unsigned gsm[];
    __shared__ unsigned tile_s;
    const int klen = QDIM / OSPLIT;            // 1024
    const int nmt  = 20 * 16;                  // 320 output tiles

    for (;;) {
        if (threadIdx.x == 0) tile_s = atomicAdd(&g_ctr_o, 1u);
        __syncthreads();
        unsigned tile = tile_s;
        if (tile >= O_TILES) return;

        int z   = (int)(tile / (unsigned)nmt);   // z-major: splits separated in time
        int bnm = (int)(tile % (unsigned)nmt);
        int bn  = (bnm % 20) * BN;
        int bm  = (bnm / 20) * BM;
        int kb  = z * klen;
        gemm_core(ah + kb, al + kb,
                  qw + (size_t)(kb >> 3) * HIDDEN,
                  sc + (size_t)(kb >> 7) * HIDDEN,
                  qz + (size_t)(kb >> 7) * HIDDEN,
                  nullptr, C, HIDDEN, QDIM, klen, bm, bn, true, gsm);
    }
}

// ======================================================================
// RoPE + split (unchanged)
// ======================================================================
__global__ __launch_bounds__(256)
void rope_split_kernel(float* __restrict__ Qb,
                       const float* __restrict__ Kf,
                       const float* __restrict__ Vf,
                       __nv_bfloat16* __restrict__ Kh, __nv_bfloat16* __restrict__ Kl,
                       __nv_bfloat16* __restrict__ Vh, __nv_bfloat16* __restrict__ Vl,
                       const float* __restrict__ cosb,
                       const float* __restrict__ sinb)
{
    int s = blockIdx.y;
    int h = blockIdx.x * 4 + (threadIdx.x >> 6);
    int d = threadIdx.x & 63;

    if (h < NH) {
        float c1 = cosb[s * HD + d],     s1 = sinb[s * HD + d];
        float c2 = cosb[s * HD + d + 64], s2 = sinb[s * HD + d + 64];
        float* base = Qb + (size_t)s * QDIM + h * HD;
        float x1 = base[d], x2 = base[d + 64];
        base[d]      = x1 * c1 - x2 * s1;
        base[d + 64] = x2 * c2 + x1 * s2;
    } else if (h < NH + NKV) {
        int kh = h - NH;
        float c1 = cosb[s * HD + d],     s1 = sinb[s * HD + d];
        float c2 = cosb[s * HD + d + 64], s2 = sinb[s * HD + d + 64];
        const float* base = Kf + (size_t)s * KVDIM + kh * HD;
        float x1 = base[d], x2 = base[d + 64];
        float y1 = x1 * c1 - x2 * s1;
        float y2 = x2 * c2 + x1 * s2;
        size_t o = (size_t)s * KVDIM + kh * HD + d;
        __nv_bfloat16 h1 = __float2bfloat16(y1);
        __nv_bfloat16 h2 = __float2bfloat16(y2);
        Kh[o] = h1;       Kl[o] = __float2bfloat16(y1 - __bfloat162float(h1));
        Kh[o + 64] = h2;  Kl[o + 64] = __float2bfloat16(y2 - __bfloat162float(h2));
    } else {
        int vh = h - NH - NKV;
        const float* base = Vf + (size_t)s * KVDIM + vh * HD;
        float x1 = base[d], x2 = base[d + 64];
        size_t o = (size_t)s * KVDIM + vh * HD + d;
        __nv_bfloat16 h1 = __float2bfloat16(x1);
        __nv_bfloat16 h2 = __float2bfloat16(x2);
        Vh[o] = h1;       Vl[o] = __float2bfloat16(x1 - __bfloat162float(h1));
        Vh[o + 64] = h2;  Vl[o + 64] = __float2bfloat16(x2 - __bfloat162float(h2));
    }
}

// ======================================================================
// bf16x3 flash attention (unchanged from R13/R15; validated)
// ======================================================================
#define FBQ 64
#define FBK 64
#define FTHREADS 128
#define KVW 68
#define FPLANE (FBK * KVW)

__global__ __launch_bounds__(FTHREADS, 2)
void flash_tc_kernel(const float* __restrict__ Q,
                     const __nv_bfloat16* __restrict__ Kh,
                     const __nv_bfloat16* __restrict__ Kl,
                     const __nv_bfloat16* __restrict__ Vh,
                     const __nv_bfloat16* __restrict__ Vl,
                     __nv_bfloat16* __restrict__ Oh,
                     __nv_bfloat16* __restrict__ Ol)
{
    extern __shared__ unsigned fsm[];
    unsigned (*KsH)[KVW] = (unsigned(*)[KVW])(fsm);
    unsigned (*KsL)[KVW] = (unsigned(*)[KVW])(fsm + FPLANE);
    unsigned (*VsH)[KVW] = (unsigned(*)[KVW])(fsm + 2 * FPLANE);
    unsigned (*VsL)[KVW] = (unsigned(*)[KVW])(fsm + 3 * FPLANE);

    int h = blockIdx.y;
    int qt = gridDim.x - 1 - blockIdx.x;
    int q0 = qt * FBQ;
    int kvh = h >> 2;
    int tid = threadIdx.x, lane = tid & 31, warp = tid >> 5;
    int t = lane & 3, g = lane >> 2;

    unsigned kbH = smem_u32(KsH), kbL = smem_u32(KsL);
    unsigned vbH = smem_u32(VsH), vbL = smem_u32(VsL);

    const __nv_bfloat16* Khb = Kh + kvh * HD;
    const __nv_bfloat16* Klb = Kl + kvh * HD;
    const __nv_bfloat16* Vhb = Vh + kvh * HD;
    const __nv_bfloat16* Vlb = Vl + kvh * HD;

    unsigned qh[8][4], ql[8][4];
    {
        const float sc = 0.08838834764831845f;
        int r0 = q0 + warp * 16 + g;
        const float* p0 = Q + (size_t)r0 * QDIM + h * HD;
        const float* p1 = p0 + 8 * QDIM;
#pragma unroll
        for (int ks = 0; ks < 8; ks++) {
            int d = ks * 16 + 2 * t;
            float2 a0 = *(const float2*)(p0 + d);
            float2 a1 = *(const float2*)(p1 + d);
            float2 a2 = *(const float2*)(p0 + d + 8);
            float2 a3 = *(const float2*)(p1 + d + 8);
            split2(a0.x * sc, a0.y * sc, qh[ks][0], ql[ks][0]);
            split2(a1.x * sc, a1.y * sc, qh[ks][1], ql[ks][1]);
            split2(a2.x * sc, a2.y * sc, qh[ks][2], ql[ks][2]);
            split2(a3.x * sc, a3.y * sc, qh[ks][3], ql[ks][3]);
        }
    }

    float m0 = -INFINITY, m1 = -INFINITY, l0s = 0.f, l1s = 0.f;
    float o_acc[16][4];
#pragma unroll
    for (int nj = 0; nj < 16; nj++)
#pragma unroll
        for (int r = 0; r < 4; r++) o_acc[nj][r] = 0.f;

    int ntiles = qt + 1;

#pragma unroll
    for (int i = 0; i < 8; i++) {
        int idx = tid + i * FTHREADS;
        int r = idx >> 4;
        int ch = idx & 15;
        size_t off = (size_t)r * KVDIM + ch * 8;
        unsigned d = (unsigned)(r * KVW + ch * 4) * 4;
        cp_async16(kbH + d, Khb + off);
        cp_async16(kbL + d, Klb + off);
    }
    CP_COMMIT();
#pragma unroll
    for (int i = 0; i < 8; i++) {
        int idx = tid + i * FTHREADS;
        int r = idx >> 4;
        int ch = idx & 15;
        size_t off = (size_t)r * KVDIM + ch * 8;
        unsigned d = (unsigned)(r * KVW + ch * 4) * 4;
        cp_async16(vbH + d, Vhb + off);
        cp_async16(vbL + d, Vlb + off);
    }
    CP_COMMIT();

    for (int tt = 0; tt < ntiles; tt++) {
        bool hasNext = (tt + 1 < ntiles);

        CP_WAIT1();
        __syncthreads();

        float s[8][4];
#pragma unroll
        for (int ni = 0; ni < 8; ni++)
#pragma unroll
            for (int r = 0; r < 4; r++) s[ni][r] = 0.f;

#pragma unroll
        for (int ks = 0; ks < 8; ks++) {
            int w = ks * 8 + t;
#pragma unroll
            for (int ni = 0; ni < 8; ni++) {
                int col = ni * 8 + g;
                unsigned bh0 = KsH[col][w], bh1 = KsH[col][w + 4];
                unsigned bl0 = KsL[col][w], bl1 = KsL[col][w + 4];
                mma_bf16(s[ni], qh[ks][0], qh[ks][1], qh[ks][2], qh[ks][3], bh0, bh1);
                mma_bf16(s[ni], qh[ks][0], qh[ks][1], qh[ks][2], qh[ks][3], bl0, bl1);
                mma_bf16(s[ni], ql[ks][0], ql[ks][1], ql[ks][2], ql[ks][3], bh0, bh1);
            }
        }
        __syncthreads();

        if (hasNext) {
            int kb1 = (tt + 1) << 6;
#pragma unroll
            for (int i = 0; i < 8; i++) {
                int idx = tid + i * FTHREADS;
                int r = idx >> 4;
                int ch = idx & 15;
                size_t off = (size_t)(kb1 + r) * KVDIM + ch * 8;
                unsigned d = (unsigned)(r * KVW + ch * 4) * 4;
                cp_async16(kbH + d, Khb + off);
                cp_async16(kbL + d, Klb + off);
            }
            CP_COMMIT();
            CP_WAIT1();
        } else {
            CP_WAIT0();
        }

        int kb = tt << 6;
        if (kb + FBK > q0) {
            int r0 = q0 + warp * 16 + g, r1 = r0 + 8;
#pragma unroll
            for (int ni = 0; ni < 8; ni++) {
                int c0 = kb + ni * 8 + 2 * t, c1 = c0 + 1;
                if (c0 > r0) s[ni][0] = -INFINITY;
                if (c1 > r0) s[ni][1] = -INFINITY;
                if (c0 > r1) s[ni][2] = -INFINITY;
                if (c1 > r1) s[ni][3] = -INFINITY;
            }
        }

        float rm0 = -INFINITY, rm1 = -INFINITY;
#pragma unroll
        for (int ni = 0; ni < 8; ni++) {
            rm0 = fmaxf(rm0, fmaxf(s[ni][0], s[ni][1]));
            rm1 = fmaxf(rm1, fmaxf(s[ni][2], s[ni][3]));
        }
        rm0 = fmaxf(rm0, __shfl_xor_sync(0xffffffffu, rm0, 1));
        rm0 = fmaxf(rm0, __shfl_xor_sync(0xffffffffu, rm0, 2));
        rm1 = fmaxf(rm1, __shfl_xor_sync(0xffffffffu, rm1, 1));
        rm1 = fmaxf(rm1, __shfl_xor_sync(0xffffffffu, rm1, 2));
        float mn0 = fmaxf(m0, rm0), mn1 = fmaxf(m1, rm1);
        float cr0 = __expf(m0 - mn0), cr1 = __expf(m1 - mn1);
        m0 = mn0; m1 = mn1;
        float ps0 = 0.f, ps1 = 0.f;
#pragma unroll
        for (int ni = 0; ni < 8; ni++) {
            s[ni][0] = __expf(s[ni][0] - mn0);
            s[ni][1] = __expf(s[ni][1] - mn0);
            s[ni][2] = __expf(s[ni][2] - mn1);
            s[ni][3] = __expf(s[ni][3] - mn1);
            ps0 += s[ni][0] + s[ni][1];
            ps1 += s[ni][2] + s[ni][3];
        }
        ps0 += __shfl_xor_sync(0xffffffffu, ps0, 1);
        ps0 += __shfl_xor_sync(0xffffffffu, ps0, 2);
        ps1 += __shfl_xor_sync(0xffffffffu, ps1, 1);
        ps1 += __shfl_xor_sync(0xffffffffu, ps1, 2);
        l0s = l0s * cr0 + ps0;
        l1s = l1s * cr1 + ps1;
#pragma unroll
        for (int nj = 0; nj < 16; nj++) {
            o_acc[nj][0] *= cr0; o_acc[nj][1] *= cr0;
            o_acc[nj][2] *= cr1; o_acc[nj][3] *= cr1;
        }

        __syncthreads();

#pragma unroll
        for (int ks2 = 0; ks2 < 4; ks2++) {
            unsigned ph[4], pl[4];
            split2(s[2 * ks2][0],     s[2 * ks2][1],     ph[0], pl[0]);
            split2(s[2 * ks2][2],     s[2 * ks2][3],     ph[1], pl[1]);
            split2(s[2 * ks2 + 1][0], s[2 * ks2 + 1][1], ph[2], pl[2]);
            split2(s[2 * ks2 + 1][2], s[2 * ks2 + 1][3], ph[3], pl[3]);
            unsigned rowb = (unsigned)(ks2 * 16 + (lane & 15)) * (KVW * 4);
#pragma unroll
            for (int nj = 0; nj < 16; nj++) {
                unsigned v0, v1, u0, u1;
                ldsm_x2_trans(v0, v1, vbH + rowb + nj * 16);
                ldsm_x2_trans(u0, u1, vbL + rowb + nj * 16);
                mma_bf16(o_acc[nj], ph[0], ph[1], ph[2], ph[3], v0, v1);
                mma_bf16(o_acc[nj], ph[0], ph[1], ph[2], ph[3], u0, u1);
                mma_bf16(o_acc[nj], pl[0], pl[1], pl[2], pl[3], v0, v1);
            }
        }
        __syncthreads();

        if (hasNext) {
            int kb1 = (tt + 1) << 6;
#pragma unroll
            for (int i = 0; i < 8; i++) {
                int idx = tid + i * FTHREADS;
                int r = idx >> 4;
                int ch = idx & 15;
                size_t off = (size_t)(kb1 + r) * KVDIM + ch * 8;
                unsigned d = (unsigned)(r * KVW + ch * 4) * 4;
                cp_async16(vbH + d, Vhb + off);
                cp_async16(vbL + d, Vlb + off);
            }
            CP_COMMIT();
        }
    }

    float inv0 = 1.f / l0s, inv1 = 1.f / l1s;
    int r0 = q0 + warp * 16 + g;
    size_t b0 = (size_t)r0 * QDIM + h * HD;
    size_t b1 = b0 + 8 * (size_t)QDIM;
#pragma unroll
    for (int nj = 0; nj < 16; nj++) {
        int d = nj * 8 + 2 * t;
        unsigned hh, ll;
        split2(o_acc[nj][0] * inv0, o_acc[nj][1] * inv0, hh, ll);
        *(unsigned*)(Oh + b0 + d) = hh;
        *(unsigned*)(Ol + b0 + d) = ll;
        split2(o_acc[nj][2] * inv1, o_acc[nj][3] * inv1, hh, ll);
        *(unsigned*)(Oh + b1 + d) = hh;
        *(unsigned*)(Ol + b1 + d) = ll;
    }
}

// ======================================================================
// Launch
// ======================================================================
extern "C" void kernel_launch(void* const* d_in, const int* in_sizes, int n_in,
                              void* d_out, int out_size)
{
    const float* x        = (const float*)d_in[0];
    const float* cosb     = (const float*)d_in[1];
    const float* sinb     = (const float*)d_in[2];
    const float* q_scales = (const float*)d_in[3];
    const float* q_bias   = (const float*)d_in[4];
    const float* k_scales = (const float*)d_in[5];
    const float* k_bias   = (const float*)d_in[6];
    const float* v_scales = (const float*)d_in[7];
    const float* v_bias   = (const float*)d_in[8];
    const float* o_scales = (const float*)d_in[9];
    const int* q_qweight  = (const int*)d_in[10];
    const int* q_qzeros   = (const int*)d_in[11];
    const int* k_qweight  = (const int*)d_in[12];
    const int* k_qzeros   = (const int*)d_in[13];
    const int* v_qweight  = (const int*)d_in[14];
    const int* v_qzeros   = (const int*)d_in[15];
    const int* o_qweight  = (const int*)d_in[16];
    const int* o_qzeros   = (const int*)d_in[17];
    float* out = (float*)d_out;

    float *pq, *pk, *pv;
    __nv_bfloat16 *pxh, *pxl, *pkh, *pkl, *pvh, *pvl, *pah, *pal;
    cudaGetSymbolAddress((void**)&pq, g_q);
    cudaGetSymbolAddress((void**)&pk, g_k);
    cudaGetSymbolAddress((void**)&pv, g_v);
    cudaGetSymbolAddress((void**)&pxh, g_xh);
    cudaGetSymbolAddress((void**)&pxl, g_xl);
    cudaGetSymbolAddress((void**)&pkh, g_kh);
    cudaGetSymbolAddress((void**)&pkl, g_kl);
    cudaGetSymbolAddress((void**)&pvh, g_vh);
    cudaGetSymbolAddress((void**)&pvl, g_vl);
    cudaGetSymbolAddress((void**)&pah, g_ah);
    cudaGetSymbolAddress((void**)&pal, g_al);

    size_t gsmem = (size_t)(2 * GBUF) * sizeof(unsigned);
    cudaFuncSetAttribute(gemm_qkv_kernel,
                         cudaFuncAttributeMaxDynamicSharedMemorySize, (int)gsmem);
    cudaFuncSetAttribute(gemm_o_kernel,
                         cudaFuncAttributeMaxDynamicSharedMemorySize, (int)gsmem);

    // reset persistent-scheduler counters (each replay)
    reset_ctr_kernel<<<1, 1>>>();

    // presplit x
    presplit_kernel<<<(S_LEN * HIDDEN / 2) / 256, 256>>>(x, pxh, pxl);

    // fused QKV projection (persistent, work-stealing)
    gemm_qkv_kernel<<<PGRID, 256, gsmem>>>(
        pxh, pxl,
        q_qweight, q_scales, q_qzeros, q_bias,
        k_qweight, k_scales, k_qzeros, k_bias,
        v_qweight, v_scales, v_qzeros, v_bias,
        pq, pk, pv);

    // RoPE (Q in-place) + K/V presplit
    {
        dim3 grid(12, S_LEN);
        rope_split_kernel<<<grid, 256>>>(pq, pk, pv, pkh, pkl, pvh, pvl, cosb, sinb);
    }

    // Flash attention
    {
        size_t smem = (size_t)(4 * FPLANE) * sizeof(unsigned);
        cudaFuncSetAttribute(flash_tc_kernel,
                             cudaFuncAttributeMaxDynamicSharedMemorySize, (int)smem);
        dim3 grid(S_LEN / FBQ, NH);
        flash_tc_kernel<<<grid, FTHREADS, smem>>>(pq, pkh, pkl, pvh, pvl, pah, pal);
    }

    // O projection: zero-init + persistent split-K=4 with atomicAdd
    {
        zero_kernel<<<(S_LEN * HIDDEN / 4) / 256, 256>>>(out);
        gemm_o_kernel<<<PGRID, 256, gsmem>>>(pah, pal, o_qweight, o_scales, o_qzeros, out);
    }
}